// round 13
// baseline (speedup 1.0000x reference)
#include <cuda_runtime.h>
#include <cstdint>

#define CB 96
#define DDIM 8
#define HDIM 56
#define WDIM 56
#define SP   (DDIM*HDIM*WDIM)   // 25088
#define HWs  (HDIM*WDIM)        // 3136
#define NT   392                // tokens per window
#define NTP  400                // padded tokens
#define NWIN 128                // total windows (B=2, 64 per batch)
#define NTOK (NWIN*NT)          // 50176

__device__ __forceinline__ float to_tf32(float x) {
    unsigned u;
    asm("cvt.rna.tf32.f32 %0, %1;" : "=r"(u) : "f"(x));
    return __uint_as_float(u);
}

__device__ __forceinline__ void mma_tf32(float* c, const unsigned* a, unsigned b0, unsigned b1) {
    asm volatile(
        "mma.sync.aligned.m16n8k8.row.col.f32.tf32.tf32.f32 "
        "{%0,%1,%2,%3}, {%4,%5,%6,%7}, {%8,%9}, {%0,%1,%2,%3};\n"
        : "+f"(c[0]), "+f"(c[1]), "+f"(c[2]), "+f"(c[3])
        : "r"(a[0]), "r"(a[1]), "r"(a[2]), "r"(a[3]), "r"(b0), "r"(b1));
}

// token id -> spatial base offset (window reverse + un-roll), channel 0
__device__ __forceinline__ size_t tok_to_spatial(int t) {
    int win = t / NT, n = t % NT;
    int bb = win >> 6; int whi = (win & 63) >> 3, wwi = win & 7;
    int dz = n/49, r = n%49, hy = r/7, wl = r%7;
    int hs = whi*7 + hy, ws = wwi*7 + wl;
    int d0 = (dz + 4) & 7;
    int h0 = hs + 3; if (h0 >= HDIM) h0 -= HDIM;
    int w0 = ws + 3; if (w0 >= WDIM) w0 -= WDIM;
    return (size_t)bb*CB*SP + (size_t)d0*HWs + h0*WDIM + w0;
}

// ---------------- scratch (device globals; no allocation) ----------------
__device__ float g_xw  [NTOK*CB];
__device__ float g_qkv0[NTOK*288];
__device__ float g_qkv1[NTOK*288];
__device__ float g_o0  [NTOK*CB];
__device__ float g_o1  [NTOK*CB];
__device__ float g_x1  [2*CB*SP];
__device__ float g_x2  [2*CB*SP];     // LN2(x1), tf32-rounded
__device__ float g_weff[9*CB*3*CB];   // [k][co], tf32-rounded
__device__ float g_beff[CB];
__device__ float g_bias[4*9*NTP*NTP]; // [class][head9][i][j]

// ---------------- LN1 + shift-roll + window partition (v2) ----------------
__global__ void k_ln1(const float* __restrict__ x,
                      const float* __restrict__ lw, const float* __restrict__ lb) {
    __shared__ float row[WDIM*97];
    __shared__ float s_mu[WDIM], s_ri[WDIM];
    int bid = blockIdx.x;
    int h = bid % HDIM; int t = bid / HDIM; int d = t & 7; int bb = t >> 3;
    const float* base = x + (size_t)bb*CB*SP + d*HWs + h*WDIM;
    for (int i = threadIdx.x; i < CB*WDIM; i += 256) {
        int c = i / WDIM, w = i % WDIM;
        row[w*97 + c] = base[(size_t)c*SP + w];
    }
    __syncthreads();
    if (threadIdx.x < 4*WDIM) {
        int w = threadIdx.x >> 2, part = threadIdx.x & 3;
        float s = 0.f, s2 = 0.f;
        const float* rp = row + w*97 + part*24;
        #pragma unroll 6
        for (int k = 0; k < 24; k++) { float v = rp[k]; s += v; s2 += v*v; }
        s  += __shfl_xor_sync(0xffffffffu, s, 1);  s  += __shfl_xor_sync(0xffffffffu, s, 2);
        s2 += __shfl_xor_sync(0xffffffffu, s2, 1); s2 += __shfl_xor_sync(0xffffffffu, s2, 2);
        if (part == 0) {
            float mu = s * (1.0f/CB);
            s_mu[w] = mu;
            s_ri[w] = rsqrtf(s2 * (1.0f/CB) - mu*mu + 1e-5f);
        }
    }
    __syncthreads();
    int ds = (d + 4) & 7;
    for (int i = threadIdx.x; i < CB*WDIM; i += 256) {
        int w = i / CB, c = i % CB;
        int hs = h - 3; if (hs < 0) hs += HDIM;
        int ws = w - 3; if (ws < 0) ws += WDIM;
        int win = bb*64 + (hs/7)*8 + (ws/7);
        int n   = ds*49 + (hs%7)*7 + (ws%7);
        g_xw[((size_t)win*NT + n)*CB + c] =
            (row[w*97 + c] - s_mu[w]) * s_ri[w] * lw[c] + lb[c];
    }
}

// ---------------- fused QKV GEMM via tf32 mma (v3: 4x2 warp split) ----------
// block: 128 M x 96 N; warps: wm=warp&3 (2 m16 tiles each), wn=warp>>2 (6 n8 tiles).
// blockIdx.z selects NAS variant (W/bias/out).
#define WSTG 104   // Ws [k][n] stride
__global__ void __launch_bounds__(256) k_qkv_mma(const float* __restrict__ A,
                                                 const float* __restrict__ W0c,
                                                 const float* __restrict__ b0c,
                                                 float* __restrict__ O0c,
                                                 const float* __restrict__ W1c,
                                                 const float* __restrict__ b1c,
                                                 float* __restrict__ O1c) {
    extern __shared__ float sm[];
    float* Ws = sm;                 // 96*WSTG
    const float* W    = blockIdx.z ? W1c : W0c;
    const float* bias = blockIdx.z ? b1c : b0c;
    float* Out        = blockIdx.z ? O1c : O0c;
    const int Ntot = 288;
    int m0 = blockIdx.x * 128;
    int n0 = blockIdx.y * 96;
    int tid = threadIdx.x, warp = tid >> 5, lane = tid & 31;
    int wm = warp & 3, wn = warp >> 2;
    int lg = lane >> 2, lq = lane & 3;

    for (int i = tid; i < 96*24; i += 256) {
        int n = i / 24, c4 = i % 24;
        float4 v = *(const float4*)(W + (size_t)(n0 + n)*CB + c4*4);
        Ws[(c4*4+0)*WSTG + n] = to_tf32(v.x);
        Ws[(c4*4+1)*WSTG + n] = to_tf32(v.y);
        Ws[(c4*4+2)*WSTG + n] = to_tf32(v.z);
        Ws[(c4*4+3)*WSTG + n] = to_tf32(v.w);
    }
    __syncthreads();

    float c[2][6][4];
    #pragma unroll
    for (int mt = 0; mt < 2; mt++)
        #pragma unroll
        for (int nt = 0; nt < 6; nt++) { c[mt][nt][0]=0.f; c[mt][nt][1]=0.f; c[mt][nt][2]=0.f; c[mt][nt][3]=0.f; }

    int r0 = m0 + (wm*2 + 0)*16 + lg;
    int r1 = m0 + (wm*2 + 1)*16 + lg;
    const float* apA0 = A + (size_t)r0*CB + lq;
    const float* apA1 = apA0 + 8*CB;
    const float* apB0 = A + (size_t)r1*CB + lq;
    const float* apB1 = apB0 + 8*CB;
    #pragma unroll
    for (int ks = 0; ks < 12; ks++) {
        int kb = ks*8;
        unsigned bf[6][2];
        #pragma unroll
        for (int nt = 0; nt < 6; nt++) {
            const float* bp = Ws + (kb + lq)*WSTG + wn*48 + nt*8 + lg;
            bf[nt][0] = __float_as_uint(bp[0]);
            bf[nt][1] = __float_as_uint(bp[4*WSTG]);
        }
        unsigned a0[4], a1[4];
        a0[0] = __float_as_uint(to_tf32(apA0[kb]));
        a0[1] = __float_as_uint(to_tf32(apA1[kb]));
        a0[2] = __float_as_uint(to_tf32(apA0[kb + 4]));
        a0[3] = __float_as_uint(to_tf32(apA1[kb + 4]));
        a1[0] = __float_as_uint(to_tf32(apB0[kb]));
        a1[1] = __float_as_uint(to_tf32(apB1[kb]));
        a1[2] = __float_as_uint(to_tf32(apB0[kb + 4]));
        a1[3] = __float_as_uint(to_tf32(apB1[kb + 4]));
        #pragma unroll
        for (int nt = 0; nt < 6; nt++) {
            mma_tf32(c[0][nt], a0, bf[nt][0], bf[nt][1]);
            mma_tf32(c[1][nt], a1, bf[nt][0], bf[nt][1]);
        }
    }

    #pragma unroll
    for (int mt = 0; mt < 2; mt++) {
        int rr = (mt == 0) ? r0 : r1;
        #pragma unroll
        for (int nt = 0; nt < 6; nt++) {
            int nc = n0 + wn*48 + nt*8 + lq*2;
            float2 bv = *(const float2*)(bias + nc);
            *(float2*)(Out + (size_t)rr*Ntot + nc)
                = make_float2(c[mt][nt][0] + bv.x, c[mt][nt][1] + bv.y);
            *(float2*)(Out + (size_t)(rr + 8)*Ntot + nc)
                = make_float2(c[mt][nt][2] + bv.x, c[mt][nt][3] + bv.y);
        }
    }
}

// ---------------- bias+mask table precompute ----------------
__global__ void k_bias(const float* __restrict__ rpb0, const float* __restrict__ rpb1) {
    int bid = blockIdx.x;
    int i = bid % NTP; int rest = bid / NTP;
    int head = rest % 9; int cls = rest / 9;
    int j = threadIdx.x;
    float v;
    if (i >= NT || j >= NT) {
        v = -1e9f;
    } else {
        int dzi = i/49, ri = i%49, hyi = ri/7, wli = ri%7;
        int dzj = j/49, rj = j%49, hyj = rj/7, wlj = rj%7;
        int idx = (dzi - dzj + 7)*169 + (hyi - hyj + 6)*13 + (wli - wlj + 6);
        float b = (head < 3) ? rpb0[idx*3 + head] : rpb1[idx*6 + head - 3];
        int ha = cls >> 1, wa = cls & 1;
        int hri = ha ? (hyi < 4 ? 1 : 2) : 0;
        int wri = wa ? (wli < 4 ? 1 : 2) : 0;
        int hrj = ha ? (hyj < 4 ? 1 : 2) : 0;
        int wrj = wa ? (wlj < 4 ? 1 : 2) : 0;
        int li = (dzi < 4 ? 0 : 1)*9 + hri*3 + wri;
        int lj = (dzj < 4 ? 0 : 1)*9 + hrj*3 + wrj;
        v = b + ((li != lj) ? -100.f : 0.f);
    }
    g_bias[((size_t)(cls*9 + head)*NTP + i)*NTP + j] = v;
}

// ---------------- windowed attention: tf32 mma + flash softmax ---------------
template<int DH, int NH, int HOFF, int MAXB>
__global__ void __launch_bounds__(256, MAXB) k_attn_mma(const float* __restrict__ qkv,
                                                        float* __restrict__ outp) {
    constexpr int KST = 408;
    constexpr int VST = (DH == 32) ? 40 : 24;
    constexpr int PST = 84;
    constexpr int NKS = DH/8;
    constexpr int NVT = DH/8;
    extern __shared__ float sm[];
    float* Ksm = sm;
    float* Vsm = Ksm + DH*KST;
    float* Psm = Vsm + NTP*VST;

    int win = blockIdx.x / NH, hd = blockIdx.x % NH;
    const float* qb = qkv + (size_t)win*NT*288;
    int tid = threadIdx.x, warp = tid >> 5, lane = tid & 31;
    int lg = lane >> 2, lq = lane & 3;
    const float scale = rsqrtf((float)DH);

    for (int idx = tid; idx < NTP*(DH/4); idx += 256) {
        int n = idx / (DH/4), d4 = (idx % (DH/4))*4;
        if (n < NT) {
            float4 kv = *(const float4*)(qb + (size_t)n*288 + 96 + hd*DH + d4);
            Ksm[(d4+0)*KST + n] = to_tf32(kv.x);
            Ksm[(d4+1)*KST + n] = to_tf32(kv.y);
            Ksm[(d4+2)*KST + n] = to_tf32(kv.z);
            Ksm[(d4+3)*KST + n] = to_tf32(kv.w);
        } else {
            Ksm[(d4+0)*KST + n] = 0.f;
            Ksm[(d4+1)*KST + n] = 0.f;
            Ksm[(d4+2)*KST + n] = 0.f;
            Ksm[(d4+3)*KST + n] = 0.f;
        }
    }
    for (int idx = tid; idx < NTP*(DH/4); idx += 256) {
        int j = idx / (DH/4), d4 = (idx % (DH/4))*4;
        float4 vv = make_float4(0.f, 0.f, 0.f, 0.f);
        if (j < NT) {
            float4 t4 = *(const float4*)(qb + (size_t)j*288 + 192 + hd*DH + d4);
            vv = make_float4(to_tf32(t4.x), to_tf32(t4.y), to_tf32(t4.z), to_tf32(t4.w));
        }
        *(float4*)(Vsm + j*VST + d4) = vv;
    }
    __syncthreads();

    int cls = ((((win & 63) >> 3) == 7) ? 2 : 0) | (((win & 7) == 7) ? 1 : 0);
    const float* bias = g_bias + (size_t)(cls*9 + HOFF + hd)*(NTP*NTP);
    float* pwarp = Psm + warp*(16*PST);

    for (int tr = warp; tr < 25; tr += 8) {
        int i0 = tr*16;
        int r0 = i0 + lg;
        int r1 = min(i0 + lg + 8, NT - 1);
        unsigned qa[NKS][4];
        #pragma unroll
        for (int ks = 0; ks < NKS; ks++) {
            int d = ks*8 + lq;
            qa[ks][0] = __float_as_uint(to_tf32(qb[(size_t)r0*288 + hd*DH + d]     * scale));
            qa[ks][1] = __float_as_uint(to_tf32(qb[(size_t)r1*288 + hd*DH + d]     * scale));
            qa[ks][2] = __float_as_uint(to_tf32(qb[(size_t)r0*288 + hd*DH + d + 4] * scale));
            qa[ks][3] = __float_as_uint(to_tf32(qb[(size_t)r1*288 + hd*DH + d + 4] * scale));
        }
        float m0 = -1e30f, m1 = -1e30f, l0 = 0.f, l1 = 0.f;
        float O[NVT][4];
        #pragma unroll
        for (int nt = 0; nt < NVT; nt++) { O[nt][0]=0.f; O[nt][1]=0.f; O[nt][2]=0.f; O[nt][3]=0.f; }

        #pragma unroll
        for (int ch = 0; ch < 5; ch++) {
            int j0 = ch*80;
            float c[10][4];
            #pragma unroll
            for (int nt = 0; nt < 10; nt++) { c[nt][0]=0.f; c[nt][1]=0.f; c[nt][2]=0.f; c[nt][3]=0.f; }
            #pragma unroll
            for (int ks = 0; ks < NKS; ks++) {
                #pragma unroll
                for (int nt = 0; nt < 10; nt++) {
                    const float* bp = Ksm + (ks*8 + lq)*KST + j0 + nt*8 + lg;
                    unsigned b0 = __float_as_uint(bp[0]);
                    unsigned b1 = __float_as_uint(bp[4*KST]);
                    mma_tf32(c[nt], qa[ks], b0, b1);
                }
            }
            #pragma unroll
            for (int nt = 0; nt < 10; nt++) {
                const float* br0 = bias + (size_t)(i0 + lg)*NTP + j0 + nt*8 + lq*2;
                float2 b0v = *(const float2*)br0;
                float2 b1v = *(const float2*)(br0 + 8*NTP);
                c[nt][0] += b0v.x; c[nt][1] += b0v.y;
                c[nt][2] += b1v.x; c[nt][3] += b1v.y;
            }
            float cm0 = -1e30f, cm1 = -1e30f;
            #pragma unroll
            for (int nt = 0; nt < 10; nt++) {
                cm0 = fmaxf(cm0, fmaxf(c[nt][0], c[nt][1]));
                cm1 = fmaxf(cm1, fmaxf(c[nt][2], c[nt][3]));
            }
            cm0 = fmaxf(cm0, __shfl_xor_sync(0xffffffffu, cm0, 1));
            cm0 = fmaxf(cm0, __shfl_xor_sync(0xffffffffu, cm0, 2));
            cm1 = fmaxf(cm1, __shfl_xor_sync(0xffffffffu, cm1, 1));
            cm1 = fmaxf(cm1, __shfl_xor_sync(0xffffffffu, cm1, 2));
            float mn0 = fmaxf(m0, cm0), mn1 = fmaxf(m1, cm1);
            float s0 = __expf(m0 - mn0), s1 = __expf(m1 - mn1);
            m0 = mn0; m1 = mn1;
            l0 *= s0; l1 *= s1;
            #pragma unroll
            for (int nt = 0; nt < NVT; nt++) {
                O[nt][0] *= s0; O[nt][1] *= s0;
                O[nt][2] *= s1; O[nt][3] *= s1;
            }
            float sum0 = 0.f, sum1 = 0.f;
            #pragma unroll
            for (int nt = 0; nt < 10; nt++) {
                c[nt][0] = to_tf32(__expf(c[nt][0] - m0)); sum0 += c[nt][0];
                c[nt][1] = to_tf32(__expf(c[nt][1] - m0)); sum0 += c[nt][1];
                c[nt][2] = to_tf32(__expf(c[nt][2] - m1)); sum1 += c[nt][2];
                c[nt][3] = to_tf32(__expf(c[nt][3] - m1)); sum1 += c[nt][3];
            }
            sum0 += __shfl_xor_sync(0xffffffffu, sum0, 1);
            sum0 += __shfl_xor_sync(0xffffffffu, sum0, 2);
            sum1 += __shfl_xor_sync(0xffffffffu, sum1, 1);
            sum1 += __shfl_xor_sync(0xffffffffu, sum1, 2);
            l0 += sum0; l1 += sum1;
            #pragma unroll
            for (int nt = 0; nt < 10; nt++) {
                int jl = nt*8 + lq*2;
                *(float2*)(pwarp + lg*PST + jl)     = make_float2(c[nt][0], c[nt][1]);
                *(float2*)(pwarp + (lg+8)*PST + jl) = make_float2(c[nt][2], c[nt][3]);
            }
            __syncwarp();
            #pragma unroll
            for (int ks = 0; ks < 10; ks++) {
                unsigned pa[4];
                const float* pp = pwarp + lg*PST + ks*8 + lq;
                pa[0] = __float_as_uint(pp[0]);
                pa[1] = __float_as_uint(pp[8*PST]);
                pa[2] = __float_as_uint(pp[4]);
                pa[3] = __float_as_uint(pp[8*PST + 4]);
                #pragma unroll
                for (int nt = 0; nt < NVT; nt++) {
                    const float* vp = Vsm + (j0 + ks*8 + lq)*VST + nt*8 + lg;
                    unsigned b0 = __float_as_uint(vp[0]);
                    unsigned b1 = __float_as_uint(vp[4*VST]);
                    mma_tf32(O[nt], pa, b0, b1);
                }
            }
            __syncwarp();
        }
        float li0 = 1.f / l0, li1 = 1.f / l1;
        int ir0 = i0 + lg, ir1 = i0 + lg + 8;
        #pragma unroll
        for (int nt = 0; nt < NVT; nt++) {
            *(float2*)(outp + ((size_t)win*NT + ir0)*CB + hd*DH + nt*8 + lq*2)
                = make_float2(O[nt][0]*li0, O[nt][1]*li0);
            if (ir1 < NT)
                *(float2*)(outp + ((size_t)win*NT + ir1)*CB + hd*DH + nt*8 + lq*2)
                    = make_float2(O[nt][2]*li1, O[nt][3]*li1);
        }
    }
}

// ---------------- fused proj0+proj1 + NAS mix + reverse + residual + LN2 -----
__global__ void __launch_bounds__(256) k_projmix(
    const float* __restrict__ o0, const float* __restrict__ o1,
    const float* __restrict__ pw0, const float* __restrict__ pb0,
    const float* __restrict__ pw1, const float* __restrict__ pb1,
    const float* __restrict__ lnw, const float* __restrict__ lnb,
    const float* __restrict__ alpha, const float* __restrict__ x) {
    extern __shared__ float sm[];
    float* Ws0 = sm;                 // 96*WSTG
    float* Ws1 = sm + 96*WSTG;
    int m0 = blockIdx.x * 128;
    int tid = threadIdx.x, warp = tid >> 5, lane = tid & 31;
    int lg = lane >> 2, lq = lane & 3;

    for (int i = tid; i < 96*24; i += 256) {
        int n = i / 24, c4 = i % 24;
        float4 v0 = *(const float4*)(pw0 + (size_t)n*CB + c4*4);
        Ws0[(c4*4+0)*WSTG + n] = to_tf32(v0.x);
        Ws0[(c4*4+1)*WSTG + n] = to_tf32(v0.y);
        Ws0[(c4*4+2)*WSTG + n] = to_tf32(v0.z);
        Ws0[(c4*4+3)*WSTG + n] = to_tf32(v0.w);
        float4 v1 = *(const float4*)(pw1 + (size_t)n*CB + c4*4);
        Ws1[(c4*4+0)*WSTG + n] = to_tf32(v1.x);
        Ws1[(c4*4+1)*WSTG + n] = to_tf32(v1.y);
        Ws1[(c4*4+2)*WSTG + n] = to_tf32(v1.z);
        Ws1[(c4*4+3)*WSTG + n] = to_tf32(v1.w);
    }
    __syncthreads();

    float c0[12][4], c1[12][4];
    #pragma unroll
    for (int nt = 0; nt < 12; nt++) {
        c0[nt][0]=0.f; c0[nt][1]=0.f; c0[nt][2]=0.f; c0[nt][3]=0.f;
        c1[nt][0]=0.f; c1[nt][1]=0.f; c1[nt][2]=0.f; c1[nt][3]=0.f;
    }

    int t0 = m0 + warp*16 + lg, t1 = t0 + 8;
    const float* a00 = o0 + (size_t)t0*CB + lq;
    const float* a01 = o0 + (size_t)t1*CB + lq;
    const float* a10 = o1 + (size_t)t0*CB + lq;
    const float* a11 = o1 + (size_t)t1*CB + lq;
    #pragma unroll
    for (int ks = 0; ks < 12; ks++) {
        int kb = ks*8;
        unsigned aA[4], aB[4];
        aA[0] = __float_as_uint(to_tf32(a00[kb]));
        aA[1] = __float_as_uint(to_tf32(a01[kb]));
        aA[2] = __float_as_uint(to_tf32(a00[kb + 4]));
        aA[3] = __float_as_uint(to_tf32(a01[kb + 4]));
        aB[0] = __float_as_uint(to_tf32(a10[kb]));
        aB[1] = __float_as_uint(to_tf32(a11[kb]));
        aB[2] = __float_as_uint(to_tf32(a10[kb + 4]));
        aB[3] = __float_as_uint(to_tf32(a11[kb + 4]));
        #pragma unroll
        for (int nt = 0; nt < 12; nt++) {
            const float* bp0 = Ws0 + (kb + lq)*WSTG + nt*8 + lg;
            mma_tf32(c0[nt], aA, __float_as_uint(bp0[0]), __float_as_uint(bp0[4*WSTG]));
            const float* bp1 = Ws1 + (kb + lq)*WSTG + nt*8 + lg;
            mma_tf32(c1[nt], aB, __float_as_uint(bp1[0]), __float_as_uint(bp1[4*WSTG]));
        }
    }

    float al0 = alpha[0], al1 = alpha[1];
    float am = fmaxf(al0, al1);
    float e0 = __expf(al0 - am), e1 = __expf(al1 - am);
    float ai = 1.f / (e0 + e1);
    float aw0 = e0*ai, aw1 = e1*ai;

    #pragma unroll
    for (int nt = 0; nt < 12; nt++) {
        int cch = nt*8 + lq*2;
        float2 b0v = *(const float2*)(pb0 + cch);
        float2 b1v = *(const float2*)(pb1 + cch);
        c0[nt][0] = aw0*(c0[nt][0] + b0v.x) + aw1*(c1[nt][0] + b1v.x);
        c0[nt][1] = aw0*(c0[nt][1] + b0v.y) + aw1*(c1[nt][1] + b1v.y);
        c0[nt][2] = aw0*(c0[nt][2] + b0v.x) + aw1*(c1[nt][2] + b1v.x);
        c0[nt][3] = aw0*(c0[nt][3] + b0v.y) + aw1*(c1[nt][3] + b1v.y);
    }

    size_t sb0 = tok_to_spatial(t0);
    size_t sb1 = tok_to_spatial(t1);
    #pragma unroll
    for (int nt = 0; nt < 12; nt++) {
        int cch = nt*8 + lq*2;
        c0[nt][0] += x[sb0 + (size_t)cch*SP];
        c0[nt][1] += x[sb0 + (size_t)(cch+1)*SP];
        c0[nt][2] += x[sb1 + (size_t)cch*SP];
        c0[nt][3] += x[sb1 + (size_t)(cch+1)*SP];
    }

    float s0 = 0.f, q0 = 0.f, s1 = 0.f, q1 = 0.f;
    #pragma unroll
    for (int nt = 0; nt < 12; nt++) {
        s0 += c0[nt][0] + c0[nt][1];
        q0 += c0[nt][0]*c0[nt][0] + c0[nt][1]*c0[nt][1];
        s1 += c0[nt][2] + c0[nt][3];
        q1 += c0[nt][2]*c0[nt][2] + c0[nt][3]*c0[nt][3];
    }
    s0 += __shfl_xor_sync(0xffffffffu, s0, 1); s0 += __shfl_xor_sync(0xffffffffu, s0, 2);
    q0 += __shfl_xor_sync(0xffffffffu, q0, 1); q0 += __shfl_xor_sync(0xffffffffu, q0, 2);
    s1 += __shfl_xor_sync(0xffffffffu, s1, 1); s1 += __shfl_xor_sync(0xffffffffu, s1, 2);
    q1 += __shfl_xor_sync(0xffffffffu, q1, 1); q1 += __shfl_xor_sync(0xffffffffu, q1, 2);
    float mu0 = s0 * (1.0f/CB), mu1 = s1 * (1.0f/CB);
    float ri0 = rsqrtf(q0 * (1.0f/CB) - mu0*mu0 + 1e-5f);
    float ri1 = rsqrtf(q1 * (1.0f/CB) - mu1*mu1 + 1e-5f);

    #pragma unroll
    for (int nt = 0; nt < 12; nt++) {
        int cch = nt*8 + lq*2;
        float w0 = lnw[cch], w1 = lnw[cch+1];
        float b0 = lnb[cch], b1 = lnb[cch+1];
        g_x1[sb0 + (size_t)cch*SP]     = c0[nt][0];
        g_x1[sb0 + (size_t)(cch+1)*SP] = c0[nt][1];
        g_x1[sb1 + (size_t)cch*SP]     = c0[nt][2];
        g_x1[sb1 + (size_t)(cch+1)*SP] = c0[nt][3];
        g_x2[sb0 + (size_t)cch*SP]     = to_tf32((c0[nt][0] - mu0)*ri0*w0 + b0);
        g_x2[sb0 + (size_t)(cch+1)*SP] = to_tf32((c0[nt][1] - mu0)*ri0*w1 + b1);
        g_x2[sb1 + (size_t)cch*SP]     = to_tf32((c0[nt][2] - mu1)*ri1*w0 + b0);
        g_x2[sb1 + (size_t)(cch+1)*SP] = to_tf32((c0[nt][3] - mu1)*ri1*w1 + b1);
    }
}

// ---------------- build effective conv weights (NAS fold, tf32-rounded) ------
__global__ void k_weff(const float* __restrict__ c3w, const float* __restrict__ c3b,
                       const float* __restrict__ c1w, const float* __restrict__ c1b,
                       const float* __restrict__ dww, const float* __restrict__ dwb,
                       const float* __restrict__ alpha) {
    float a[4]; float m = -1e30f;
    #pragma unroll
    for (int i = 0; i < 4; i++) { a[i] = alpha[i]; m = fmaxf(m, a[i]); }
    float s = 0.f;
    #pragma unroll
    for (int i = 0; i < 4; i++) { a[i] = __expf(a[i] - m); s += a[i]; }
    float inv = 1.f / s;
    #pragma unroll
    for (int i = 0; i < 4; i++) a[i] *= inv;
    int total = CB*CB*27;
    for (int idx = blockIdx.x*blockDim.x + threadIdx.x; idx < total; idx += gridDim.x*blockDim.x) {
        int t = idx % 27; int rest = idx / 27; int ci = rest % CB; int co = rest / CB;
        float val = a[0] * c3w[idx];
        if (t == 13)            val += a[1] * c1w[co*CB + ci];
        if (ci == co)           val += a[2] * dww[co*27 + t];
        if (t == 13 && ci == co) val += a[3];
        int tt = t / 3, tw = t % 3;
        g_weff[(((size_t)tt*CB + ci)*3 + tw)*CB + co] = to_tf32(val);
    }
    int gid = blockIdx.x*blockDim.x + threadIdx.x;
    if (gid < CB) g_beff[gid] = a[0]*c3b[gid] + a[1]*c1b[gid] + a[2]*dwb[gid];
}

// ---------------- FFN as tf32 implicit-GEMM mma + residual (double-buffered) -
#define KCH 32
#define AST 104
#define BST 232
#define FBUF (KCH*AST + KCH*BST)   // 10752 floats per buffer

__global__ void __launch_bounds__(256) k_ffn_mma(float* __restrict__ out) {
    extern __shared__ float sm[];
    int bid = blockIdx.x;
    int h4 = bid % 14; int t = bid / 14; int d = t & 7; int bb = t >> 3;
    int h0 = h4*4;
    int tid = threadIdx.x;
    int warp = tid >> 5, lane = tid & 31;
    int wm = warp >> 2, wn = warp & 3;
    int lg = lane >> 2, lq = lane & 3;
    int kk = tid >> 3, nlane = tid & 7;

    float acc[3][7][4];
    #pragma unroll
    for (int mt = 0; mt < 3; mt++) {
        int m = wm*48 + mt*16 + lg;
        float b0 = g_beff[m], b8 = g_beff[m + 8];
        #pragma unroll
        for (int nt = 0; nt < 7; nt++) {
            acc[mt][nt][0] = b0; acc[mt][nt][1] = b0;
            acc[mt][nt][2] = b8; acc[mt][nt][3] = b8;
        }
    }

    auto stage = [&](int buf, int kc) {
        float* As = sm + buf*FBUF;
        float* Bs = As + KCH*AST;
        #pragma unroll
        for (int s = 0; s < 12; s++) {
            int i = tid + s*256;
            int k = i / 96, co = i % 96;
            As[k*AST + co] = g_weff[(size_t)(kc*KCH + k)*CB + co];
        }
        int kg = kc*KCH + kk;
        int tt = kg / 288; int r = kg % 288; int ci = r / 3; int tw = r % 3;
        int td = tt / 3, th = tt % 3;
        int sd = d + td - 1;
        bool dok = (unsigned)sd < 8u;
        const float* rowp[4]; bool rok[4];
        #pragma unroll
        for (int hr = 0; hr < 4; hr++) {
            int sh = h0 + hr + th - 1;
            rok[hr] = dok && (unsigned)sh < 56u;
            rowp[hr] = g_x2 + ((size_t)(bb*CB + ci)*DDIM + sd)*HWs + sh*WDIM + (tw - 1);
        }
        float* bdst = Bs + kk*BST;
        #pragma unroll
        for (int j = 0; j < 28; j++) {
            const int hr = (j*8) / 56;
            const int wb = (j*8) % 56;
            int w = wb + nlane;
            bool ok = rok[hr] && ((unsigned)(w + tw - 1) < 56u);
            bdst[j*8 + nlane] = ok ? rowp[hr][w] : 0.f;
        }
    };

    stage(0, 0);
    for (int kc = 0; kc < 81; kc++) {
        __syncthreads();
        if (kc < 80) stage((kc + 1) & 1, kc + 1);
        const float* As = sm + (kc & 1)*FBUF;
        const float* Bs = As + KCH*AST;
        #pragma unroll
        for (int k8 = 0; k8 < 4; k8++) {
            int kb = k8*8;
            unsigned a[3][4];
            #pragma unroll
            for (int mt = 0; mt < 3; mt++) {
                const float* ap = As + (kb + lq)*AST + wm*48 + mt*16 + lg;
                a[mt][0] = __float_as_uint(ap[0]);
                a[mt][1] = __float_as_uint(ap[8]);
                a[mt][2] = __float_as_uint(ap[4*AST]);
                a[mt][3] = __float_as_uint(ap[4*AST + 8]);
            }
            #pragma unroll
            for (int nt = 0; nt < 7; nt++) {
                const float* bp = Bs + (kb + lq)*BST + wn*56 + nt*8 + lg;
                unsigned b0 = __float_as_uint(bp[0]);
                unsigned b1 = __float_as_uint(bp[4*BST]);
                mma_tf32(acc[0][nt], a[0], b0, b1);
                mma_tf32(acc[1][nt], a[1], b0, b1);
                mma_tf32(acc[2][nt], a[2], b0, b1);
            }
        }
    }

    int hrow = h0 + wn;
    #pragma unroll
    for (int mt = 0; mt < 3; mt++) {
        int m = wm*48 + mt*16 + lg;
        size_t base = ((size_t)(bb*CB + m)*DDIM + d)*HWs + hrow*WDIM;
        #pragma unroll
        for (int nt = 0; nt < 7; nt++) {
            int w0 = nt*8 + lq*2;
            size_t i0 = base + w0;
            size_t i1 = i0 + (size_t)8*SP;
            float2 r0 = *(const float2*)(g_x1 + i0);
            float2 r1 = *(const float2*)(g_x1 + i1);
            float2 o0 = make_float2(r0.x + acc[mt][nt][0], r0.y + acc[mt][nt][1]);
            float2 o1 = make_float2(r1.x + acc[mt][nt][2], r1.y + acc[mt][nt][3]);
            *(float2*)(out + i0) = o0;
            *(float2*)(out + i1) = o1;
        }
    }
}

// ---------------- host launch ----------------
extern "C" void kernel_launch(void* const* d_in, const int* in_sizes, int n_in,
                              void* d_out, int out_size) {
    (void)in_sizes; (void)n_in; (void)out_size;
    const float* x      = (const float*)d_in[0];
    const float* ln1w   = (const float*)d_in[1];
    const float* ln1b   = (const float*)d_in[2];
    const float* ln2w   = (const float*)d_in[3];
    const float* ln2b   = (const float*)d_in[4];
    const float* qkvw0  = (const float*)d_in[5];
    const float* qkvb0  = (const float*)d_in[6];
    const float* projw0 = (const float*)d_in[7];
    const float* projb0 = (const float*)d_in[8];
    const float* rpb0   = (const float*)d_in[9];
    const float* qkvw1  = (const float*)d_in[10];
    const float* qkvb1  = (const float*)d_in[11];
    const float* projw1 = (const float*)d_in[12];
    const float* projb1 = (const float*)d_in[13];
    const float* rpb1   = (const float*)d_in[14];
    const float* alphaA = (const float*)d_in[15];
    const float* c3w    = (const float*)d_in[16];
    const float* c3b    = (const float*)d_in[17];
    const float* c1w    = (const float*)d_in[18];
    const float* c1b    = (const float*)d_in[19];
    const float* dww    = (const float*)d_in[20];
    const float* dwb    = (const float*)d_in[21];
    const float* alphaF = (const float*)d_in[22];
    float* out = (float*)d_out;

    float *p_xw, *p_q0, *p_q1, *p_o0, *p_o1;
    cudaGetSymbolAddress((void**)&p_xw, g_xw);
    cudaGetSymbolAddress((void**)&p_q0, g_qkv0);
    cudaGetSymbolAddress((void**)&p_q1, g_qkv1);
    cudaGetSymbolAddress((void**)&p_o0, g_o0);
    cudaGetSymbolAddress((void**)&p_o1, g_o1);

    int smG  = (96*WSTG) * 4;                     // 39936 B
    int smP  = (2*96*WSTG) * 4;                   // 79872 B
    int smA0 = (32*408 + NTP*40 + 8*16*84) * 4;   // 159232 B
    int smA1 = (16*408 + NTP*24 + 8*16*84) * 4;   // 107520 B
    int smF  = 2*FBUF*4;                          // 86016 B
    cudaFuncSetAttribute((const void*)k_qkv_mma,
                         cudaFuncAttributeMaxDynamicSharedMemorySize, smG);
    cudaFuncSetAttribute((const void*)k_projmix,
                         cudaFuncAttributeMaxDynamicSharedMemorySize, smP);
    cudaFuncSetAttribute((const void*)k_attn_mma<32,3,0,1>,
                         cudaFuncAttributeMaxDynamicSharedMemorySize, smA0);
    cudaFuncSetAttribute((const void*)k_attn_mma<16,6,3,2>,
                         cudaFuncAttributeMaxDynamicSharedMemorySize, smA1);
    cudaFuncSetAttribute((const void*)k_ffn_mma,
                         cudaFuncAttributeMaxDynamicSharedMemorySize, smF);

    // 0) bias+mask table
    k_bias<<<4*9*NTP, NTP>>>(rpb0, rpb1);

    // 1) LN1 + roll + window partition
    k_ln1<<<2*DDIM*HDIM, 256>>>(x, ln1w, ln1b);

    // 2) both QKV GEMMs in one launch (tf32 mma, 4x2 warp split)
    dim3 gq(NTOK/128, 3, 2);
    k_qkv_mma<<<gq, 256, smG>>>(p_xw, qkvw0, qkvb0, p_q0, qkvw1, qkvb1, p_q1);

    // 3) windowed attention (tf32 mma, flash softmax)
    k_attn_mma<32,3,0,1><<<NWIN*3, 256, smA0>>>(p_q0, p_o0);
    k_attn_mma<16,6,3,2><<<NWIN*6, 256, smA1>>>(p_q1, p_o1);

    // 4) fused proj + mix + reverse + residual + LN2
    k_projmix<<<NTOK/128, 256, smP>>>(p_o0, p_o1, projw0, projb0, projw1, projb1,
                                      ln2w, ln2b, alphaA, x);

    // 5) effective conv weights (tf32) + tensor-core FFN + residual
    k_weff<<<128, 256>>>(c3w, c3b, c1w, c1b, dww, dwb, alphaF);
    k_ffn_mma<<<2*DDIM*(HDIM/4), 256, smF>>>(out);
}

// round 14
// speedup vs baseline: 1.0389x; 1.0389x over previous
#include <cuda_runtime.h>
#include <cstdint>

#define CB 96
#define DDIM 8
#define HDIM 56
#define WDIM 56
#define SP   (DDIM*HDIM*WDIM)   // 25088
#define HWs  (HDIM*WDIM)        // 3136
#define NT   392                // tokens per window
#define NTP  400                // padded tokens
#define NWIN 128                // total windows (B=2, 64 per batch)
#define NTOK (NWIN*NT)          // 50176

__device__ __forceinline__ float to_tf32(float x) {
    unsigned u;
    asm("cvt.rna.tf32.f32 %0, %1;" : "=r"(u) : "f"(x));
    return __uint_as_float(u);
}

__device__ __forceinline__ void mma_tf32(float* c, const unsigned* a, unsigned b0, unsigned b1) {
    asm volatile(
        "mma.sync.aligned.m16n8k8.row.col.f32.tf32.tf32.f32 "
        "{%0,%1,%2,%3}, {%4,%5,%6,%7}, {%8,%9}, {%0,%1,%2,%3};\n"
        : "+f"(c[0]), "+f"(c[1]), "+f"(c[2]), "+f"(c[3])
        : "r"(a[0]), "r"(a[1]), "r"(a[2]), "r"(a[3]), "r"(b0), "r"(b1));
}

// token id -> spatial base offset (window reverse + un-roll), channel 0
__device__ __forceinline__ size_t tok_to_spatial(int t) {
    int win = t / NT, n = t % NT;
    int bb = win >> 6; int whi = (win & 63) >> 3, wwi = win & 7;
    int dz = n/49, r = n%49, hy = r/7, wl = r%7;
    int hs = whi*7 + hy, ws = wwi*7 + wl;
    int d0 = (dz + 4) & 7;
    int h0 = hs + 3; if (h0 >= HDIM) h0 -= HDIM;
    int w0 = ws + 3; if (w0 >= WDIM) w0 -= WDIM;
    return (size_t)bb*CB*SP + (size_t)d0*HWs + h0*WDIM + w0;
}

// ---------------- scratch (device globals; no allocation) ----------------
__device__ float g_xw  [NTOK*CB];
__device__ float g_qkv0[NTOK*288];
__device__ float g_qkv1[NTOK*288];
__device__ float g_o0  [NTOK*CB];
__device__ float g_o1  [NTOK*CB];
__device__ float g_x1  [2*CB*SP];
__device__ float g_x2  [2*CB*SP];     // LN2(x1), tf32-rounded
__device__ float g_weff[9*CB*3*CB];   // [k][co], tf32-rounded
__device__ float g_beff[CB];
__device__ float g_bias[4*9*NTP*NTP]; // [class][head9][i][j]

// ---------------- LN1 + shift-roll + window partition (v2) ----------------
__global__ void k_ln1(const float* __restrict__ x,
                      const float* __restrict__ lw, const float* __restrict__ lb) {
    __shared__ float row[WDIM*97];
    __shared__ float s_mu[WDIM], s_ri[WDIM];
    int bid = blockIdx.x;
    int h = bid % HDIM; int t = bid / HDIM; int d = t & 7; int bb = t >> 3;
    const float* base = x + (size_t)bb*CB*SP + d*HWs + h*WDIM;
    for (int i = threadIdx.x; i < CB*WDIM; i += 256) {
        int c = i / WDIM, w = i % WDIM;
        row[w*97 + c] = base[(size_t)c*SP + w];
    }
    __syncthreads();
    if (threadIdx.x < 4*WDIM) {
        int w = threadIdx.x >> 2, part = threadIdx.x & 3;
        float s = 0.f, s2 = 0.f;
        const float* rp = row + w*97 + part*24;
        #pragma unroll 6
        for (int k = 0; k < 24; k++) { float v = rp[k]; s += v; s2 += v*v; }
        s  += __shfl_xor_sync(0xffffffffu, s, 1);  s  += __shfl_xor_sync(0xffffffffu, s, 2);
        s2 += __shfl_xor_sync(0xffffffffu, s2, 1); s2 += __shfl_xor_sync(0xffffffffu, s2, 2);
        if (part == 0) {
            float mu = s * (1.0f/CB);
            s_mu[w] = mu;
            s_ri[w] = rsqrtf(s2 * (1.0f/CB) - mu*mu + 1e-5f);
        }
    }
    __syncthreads();
    int ds = (d + 4) & 7;
    for (int i = threadIdx.x; i < CB*WDIM; i += 256) {
        int w = i / CB, c = i % CB;
        int hs = h - 3; if (hs < 0) hs += HDIM;
        int ws = w - 3; if (ws < 0) ws += WDIM;
        int win = bb*64 + (hs/7)*8 + (ws/7);
        int n   = ds*49 + (hs%7)*7 + (ws%7);
        g_xw[((size_t)win*NT + n)*CB + c] =
            (row[w*97 + c] - s_mu[w]) * s_ri[w] * lw[c] + lb[c];
    }
}

// ---------------- GEMM via tf32 mma (R10 version: A direct from global) ------
// block: 128 M x 96 N; 8 warps; warp = m16 row x 12 n8 tiles. K=96.
#define WSTG 104   // Ws [k][n] stride
__global__ void __launch_bounds__(256) k_gemm_mma(const float* __restrict__ A,
                                                  const float* __restrict__ W,
                                                  const float* __restrict__ bias,
                                                  float* __restrict__ Out, int Ntot) {
    extern __shared__ float sm[];
    float* Ws = sm;                 // 96*WSTG
    int m0 = blockIdx.x * 128;
    int n0 = blockIdx.y * 96;
    int tid = threadIdx.x, warp = tid >> 5, lane = tid & 31;
    int lg = lane >> 2, lq = lane & 3;

    for (int i = tid; i < 96*24; i += 256) {
        int n = i / 24, c4 = i % 24;
        float4 v = *(const float4*)(W + (size_t)(n0 + n)*CB + c4*4);
        Ws[(c4*4+0)*WSTG + n] = to_tf32(v.x);
        Ws[(c4*4+1)*WSTG + n] = to_tf32(v.y);
        Ws[(c4*4+2)*WSTG + n] = to_tf32(v.z);
        Ws[(c4*4+3)*WSTG + n] = to_tf32(v.w);
    }
    __syncthreads();

    float c[12][4];
    #pragma unroll
    for (int nt = 0; nt < 12; nt++) { c[nt][0]=0.f; c[nt][1]=0.f; c[nt][2]=0.f; c[nt][3]=0.f; }

    int r0 = m0 + warp*16 + lg;
    const float* ap0 = A + (size_t)r0*CB + lq;
    const float* ap1 = ap0 + 8*CB;
    #pragma unroll
    for (int ks = 0; ks < 12; ks++) {
        int kb = ks*8;
        unsigned a[4];
        a[0] = __float_as_uint(to_tf32(ap0[kb]));
        a[1] = __float_as_uint(to_tf32(ap1[kb]));
        a[2] = __float_as_uint(to_tf32(ap0[kb + 4]));
        a[3] = __float_as_uint(to_tf32(ap1[kb + 4]));
        #pragma unroll
        for (int nt = 0; nt < 12; nt++) {
            const float* bp = Ws + (kb + lq)*WSTG + nt*8 + lg;
            unsigned b0 = __float_as_uint(bp[0]);
            unsigned b1 = __float_as_uint(bp[4*WSTG]);
            mma_tf32(c[nt], a, b0, b1);
        }
    }

    #pragma unroll
    for (int nt = 0; nt < 12; nt++) {
        int nc = n0 + nt*8 + lq*2;
        float2 bv = *(const float2*)(bias + nc);
        *(float2*)(Out + (size_t)r0*Ntot + nc)
            = make_float2(c[nt][0] + bv.x, c[nt][1] + bv.y);
        *(float2*)(Out + (size_t)(r0 + 8)*Ntot + nc)
            = make_float2(c[nt][2] + bv.x, c[nt][3] + bv.y);
    }
}

// ---------------- bias+mask table precompute ----------------
__global__ void k_bias(const float* __restrict__ rpb0, const float* __restrict__ rpb1) {
    int bid = blockIdx.x;
    int i = bid % NTP; int rest = bid / NTP;
    int head = rest % 9; int cls = rest / 9;
    int j = threadIdx.x;
    float v;
    if (i >= NT || j >= NT) {
        v = -1e9f;
    } else {
        int dzi = i/49, ri = i%49, hyi = ri/7, wli = ri%7;
        int dzj = j/49, rj = j%49, hyj = rj/7, wlj = rj%7;
        int idx = (dzi - dzj + 7)*169 + (hyi - hyj + 6)*13 + (wli - wlj + 6);
        float b = (head < 3) ? rpb0[idx*3 + head] : rpb1[idx*6 + head - 3];
        int ha = cls >> 1, wa = cls & 1;
        int hri = ha ? (hyi < 4 ? 1 : 2) : 0;
        int wri = wa ? (wli < 4 ? 1 : 2) : 0;
        int hrj = ha ? (hyj < 4 ? 1 : 2) : 0;
        int wrj = wa ? (wlj < 4 ? 1 : 2) : 0;
        int li = (dzi < 4 ? 0 : 1)*9 + hri*3 + wri;
        int lj = (dzj < 4 ? 0 : 1)*9 + hrj*3 + wrj;
        v = b + ((li != lj) ? -100.f : 0.f);
    }
    g_bias[((size_t)(cls*9 + head)*NTP + i)*NTP + j] = v;
}

// ---------------- windowed attention: tf32 mma + flash softmax ---------------
// NTHR threads (NW = NTHR/32 warps). Warp handles tile rows tr = warp, warp+NW, ...
template<int DH, int NH, int HOFF, int MAXB, int NTHR>
__global__ void __launch_bounds__(NTHR, MAXB) k_attn_mma(const float* __restrict__ qkv,
                                                         float* __restrict__ outp) {
    constexpr int NW  = NTHR/32;
    constexpr int KST = 408;
    constexpr int VST = (DH == 32) ? 40 : 24;
    constexpr int PST = 84;
    constexpr int NKS = DH/8;
    constexpr int NVT = DH/8;
    extern __shared__ float sm[];
    float* Ksm = sm;
    float* Vsm = Ksm + DH*KST;
    float* Psm = Vsm + NTP*VST;

    int win = blockIdx.x / NH, hd = blockIdx.x % NH;
    const float* qb = qkv + (size_t)win*NT*288;
    int tid = threadIdx.x, warp = tid >> 5, lane = tid & 31;
    int lg = lane >> 2, lq = lane & 3;
    const float scale = rsqrtf((float)DH);

    for (int idx = tid; idx < NTP*(DH/4); idx += NTHR) {
        int n = idx / (DH/4), d4 = (idx % (DH/4))*4;
        if (n < NT) {
            float4 kv = *(const float4*)(qb + (size_t)n*288 + 96 + hd*DH + d4);
            Ksm[(d4+0)*KST + n] = to_tf32(kv.x);
            Ksm[(d4+1)*KST + n] = to_tf32(kv.y);
            Ksm[(d4+2)*KST + n] = to_tf32(kv.z);
            Ksm[(d4+3)*KST + n] = to_tf32(kv.w);
        } else {
            Ksm[(d4+0)*KST + n] = 0.f;
            Ksm[(d4+1)*KST + n] = 0.f;
            Ksm[(d4+2)*KST + n] = 0.f;
            Ksm[(d4+3)*KST + n] = 0.f;
        }
    }
    for (int idx = tid; idx < NTP*(DH/4); idx += NTHR) {
        int j = idx / (DH/4), d4 = (idx % (DH/4))*4;
        float4 vv = make_float4(0.f, 0.f, 0.f, 0.f);
        if (j < NT) {
            float4 t4 = *(const float4*)(qb + (size_t)j*288 + 192 + hd*DH + d4);
            vv = make_float4(to_tf32(t4.x), to_tf32(t4.y), to_tf32(t4.z), to_tf32(t4.w));
        }
        *(float4*)(Vsm + j*VST + d4) = vv;
    }
    __syncthreads();

    int cls = ((((win & 63) >> 3) == 7) ? 2 : 0) | (((win & 7) == 7) ? 1 : 0);
    const float* bias = g_bias + (size_t)(cls*9 + HOFF + hd)*(NTP*NTP);
    float* pwarp = Psm + warp*(16*PST);

    for (int tr = warp; tr < 25; tr += NW) {
        int i0 = tr*16;
        int r0 = i0 + lg;
        int r1 = min(i0 + lg + 8, NT - 1);
        unsigned qa[NKS][4];
        #pragma unroll
        for (int ks = 0; ks < NKS; ks++) {
            int d = ks*8 + lq;
            qa[ks][0] = __float_as_uint(to_tf32(qb[(size_t)r0*288 + hd*DH + d]     * scale));
            qa[ks][1] = __float_as_uint(to_tf32(qb[(size_t)r1*288 + hd*DH + d]     * scale));
            qa[ks][2] = __float_as_uint(to_tf32(qb[(size_t)r0*288 + hd*DH + d + 4] * scale));
            qa[ks][3] = __float_as_uint(to_tf32(qb[(size_t)r1*288 + hd*DH + d + 4] * scale));
        }
        float m0 = -1e30f, m1 = -1e30f, l0 = 0.f, l1 = 0.f;
        float O[NVT][4];
        #pragma unroll
        for (int nt = 0; nt < NVT; nt++) { O[nt][0]=0.f; O[nt][1]=0.f; O[nt][2]=0.f; O[nt][3]=0.f; }

        #pragma unroll
        for (int ch = 0; ch < 5; ch++) {
            int j0 = ch*80;
            float c[10][4];
            #pragma unroll
            for (int nt = 0; nt < 10; nt++) { c[nt][0]=0.f; c[nt][1]=0.f; c[nt][2]=0.f; c[nt][3]=0.f; }
            #pragma unroll
            for (int ks = 0; ks < NKS; ks++) {
                #pragma unroll
                for (int nt = 0; nt < 10; nt++) {
                    const float* bp = Ksm + (ks*8 + lq)*KST + j0 + nt*8 + lg;
                    unsigned b0 = __float_as_uint(bp[0]);
                    unsigned b1 = __float_as_uint(bp[4*KST]);
                    mma_tf32(c[nt], qa[ks], b0, b1);
                }
            }
            #pragma unroll
            for (int nt = 0; nt < 10; nt++) {
                const float* br0 = bias + (size_t)(i0 + lg)*NTP + j0 + nt*8 + lq*2;
                float2 b0v = *(const float2*)br0;
                float2 b1v = *(const float2*)(br0 + 8*NTP);
                c[nt][0] += b0v.x; c[nt][1] += b0v.y;
                c[nt][2] += b1v.x; c[nt][3] += b1v.y;
            }
            float cm0 = -1e30f, cm1 = -1e30f;
            #pragma unroll
            for (int nt = 0; nt < 10; nt++) {
                cm0 = fmaxf(cm0, fmaxf(c[nt][0], c[nt][1]));
                cm1 = fmaxf(cm1, fmaxf(c[nt][2], c[nt][3]));
            }
            cm0 = fmaxf(cm0, __shfl_xor_sync(0xffffffffu, cm0, 1));
            cm0 = fmaxf(cm0, __shfl_xor_sync(0xffffffffu, cm0, 2));
            cm1 = fmaxf(cm1, __shfl_xor_sync(0xffffffffu, cm1, 1));
            cm1 = fmaxf(cm1, __shfl_xor_sync(0xffffffffu, cm1, 2));
            float mn0 = fmaxf(m0, cm0), mn1 = fmaxf(m1, cm1);
            float s0 = __expf(m0 - mn0), s1 = __expf(m1 - mn1);
            m0 = mn0; m1 = mn1;
            l0 *= s0; l1 *= s1;
            #pragma unroll
            for (int nt = 0; nt < NVT; nt++) {
                O[nt][0] *= s0; O[nt][1] *= s0;
                O[nt][2] *= s1; O[nt][3] *= s1;
            }
            float sum0 = 0.f, sum1 = 0.f;
            #pragma unroll
            for (int nt = 0; nt < 10; nt++) {
                c[nt][0] = to_tf32(__expf(c[nt][0] - m0)); sum0 += c[nt][0];
                c[nt][1] = to_tf32(__expf(c[nt][1] - m0)); sum0 += c[nt][1];
                c[nt][2] = to_tf32(__expf(c[nt][2] - m1)); sum1 += c[nt][2];
                c[nt][3] = to_tf32(__expf(c[nt][3] - m1)); sum1 += c[nt][3];
            }
            sum0 += __shfl_xor_sync(0xffffffffu, sum0, 1);
            sum0 += __shfl_xor_sync(0xffffffffu, sum0, 2);
            sum1 += __shfl_xor_sync(0xffffffffu, sum1, 1);
            sum1 += __shfl_xor_sync(0xffffffffu, sum1, 2);
            l0 += sum0; l1 += sum1;
            #pragma unroll
            for (int nt = 0; nt < 10; nt++) {
                int jl = nt*8 + lq*2;
                *(float2*)(pwarp + lg*PST + jl)     = make_float2(c[nt][0], c[nt][1]);
                *(float2*)(pwarp + (lg+8)*PST + jl) = make_float2(c[nt][2], c[nt][3]);
            }
            __syncwarp();
            #pragma unroll
            for (int ks = 0; ks < 10; ks++) {
                unsigned pa[4];
                const float* pp = pwarp + lg*PST + ks*8 + lq;
                pa[0] = __float_as_uint(pp[0]);
                pa[1] = __float_as_uint(pp[8*PST]);
                pa[2] = __float_as_uint(pp[4]);
                pa[3] = __float_as_uint(pp[8*PST + 4]);
                #pragma unroll
                for (int nt = 0; nt < NVT; nt++) {
                    const float* vp = Vsm + (j0 + ks*8 + lq)*VST + nt*8 + lg;
                    unsigned b0 = __float_as_uint(vp[0]);
                    unsigned b1 = __float_as_uint(vp[4*VST]);
                    mma_tf32(O[nt], pa, b0, b1);
                }
            }
            __syncwarp();
        }
        float li0 = 1.f / l0, li1 = 1.f / l1;
        int ir0 = i0 + lg, ir1 = i0 + lg + 8;
        #pragma unroll
        for (int nt = 0; nt < NVT; nt++) {
            *(float2*)(outp + ((size_t)win*NT + ir0)*CB + hd*DH + nt*8 + lq*2)
                = make_float2(O[nt][0]*li0, O[nt][1]*li0);
            if (ir1 < NT)
                *(float2*)(outp + ((size_t)win*NT + ir1)*CB + hd*DH + nt*8 + lq*2)
                    = make_float2(O[nt][2]*li1, O[nt][3]*li1);
        }
    }
}

// ---------------- fused proj0+proj1 + NAS mix + reverse + residual + LN2 -----
__global__ void __launch_bounds__(256) k_projmix(
    const float* __restrict__ o0, const float* __restrict__ o1,
    const float* __restrict__ pw0, const float* __restrict__ pb0,
    const float* __restrict__ pw1, const float* __restrict__ pb1,
    const float* __restrict__ lnw, const float* __restrict__ lnb,
    const float* __restrict__ alpha, const float* __restrict__ x) {
    extern __shared__ float sm[];
    float* Ws0 = sm;                 // 96*WSTG
    float* Ws1 = sm + 96*WSTG;
    int m0 = blockIdx.x * 128;
    int tid = threadIdx.x, warp = tid >> 5, lane = tid & 31;
    int lg = lane >> 2, lq = lane & 3;

    for (int i = tid; i < 96*24; i += 256) {
        int n = i / 24, c4 = i % 24;
        float4 v0 = *(const float4*)(pw0 + (size_t)n*CB + c4*4);
        Ws0[(c4*4+0)*WSTG + n] = to_tf32(v0.x);
        Ws0[(c4*4+1)*WSTG + n] = to_tf32(v0.y);
        Ws0[(c4*4+2)*WSTG + n] = to_tf32(v0.z);
        Ws0[(c4*4+3)*WSTG + n] = to_tf32(v0.w);
        float4 v1 = *(const float4*)(pw1 + (size_t)n*CB + c4*4);
        Ws1[(c4*4+0)*WSTG + n] = to_tf32(v1.x);
        Ws1[(c4*4+1)*WSTG + n] = to_tf32(v1.y);
        Ws1[(c4*4+2)*WSTG + n] = to_tf32(v1.z);
        Ws1[(c4*4+3)*WSTG + n] = to_tf32(v1.w);
    }
    __syncthreads();

    float c0[12][4], c1[12][4];
    #pragma unroll
    for (int nt = 0; nt < 12; nt++) {
        c0[nt][0]=0.f; c0[nt][1]=0.f; c0[nt][2]=0.f; c0[nt][3]=0.f;
        c1[nt][0]=0.f; c1[nt][1]=0.f; c1[nt][2]=0.f; c1[nt][3]=0.f;
    }

    int t0 = m0 + warp*16 + lg, t1 = t0 + 8;
    const float* a00 = o0 + (size_t)t0*CB + lq;
    const float* a01 = o0 + (size_t)t1*CB + lq;
    const float* a10 = o1 + (size_t)t0*CB + lq;
    const float* a11 = o1 + (size_t)t1*CB + lq;
    #pragma unroll
    for (int ks = 0; ks < 12; ks++) {
        int kb = ks*8;
        unsigned aA[4], aB[4];
        aA[0] = __float_as_uint(to_tf32(a00[kb]));
        aA[1] = __float_as_uint(to_tf32(a01[kb]));
        aA[2] = __float_as_uint(to_tf32(a00[kb + 4]));
        aA[3] = __float_as_uint(to_tf32(a01[kb + 4]));
        aB[0] = __float_as_uint(to_tf32(a10[kb]));
        aB[1] = __float_as_uint(to_tf32(a11[kb]));
        aB[2] = __float_as_uint(to_tf32(a10[kb + 4]));
        aB[3] = __float_as_uint(to_tf32(a11[kb + 4]));
        #pragma unroll
        for (int nt = 0; nt < 12; nt++) {
            const float* bp0 = Ws0 + (kb + lq)*WSTG + nt*8 + lg;
            mma_tf32(c0[nt], aA, __float_as_uint(bp0[0]), __float_as_uint(bp0[4*WSTG]));
            const float* bp1 = Ws1 + (kb + lq)*WSTG + nt*8 + lg;
            mma_tf32(c1[nt], aB, __float_as_uint(bp1[0]), __float_as_uint(bp1[4*WSTG]));
        }
    }

    float al0 = alpha[0], al1 = alpha[1];
    float am = fmaxf(al0, al1);
    float e0 = __expf(al0 - am), e1 = __expf(al1 - am);
    float ai = 1.f / (e0 + e1);
    float aw0 = e0*ai, aw1 = e1*ai;

    #pragma unroll
    for (int nt = 0; nt < 12; nt++) {
        int cch = nt*8 + lq*2;
        float2 b0v = *(const float2*)(pb0 + cch);
        float2 b1v = *(const float2*)(pb1 + cch);
        c0[nt][0] = aw0*(c0[nt][0] + b0v.x) + aw1*(c1[nt][0] + b1v.x);
        c0[nt][1] = aw0*(c0[nt][1] + b0v.y) + aw1*(c1[nt][1] + b1v.y);
        c0[nt][2] = aw0*(c0[nt][2] + b0v.x) + aw1*(c1[nt][2] + b1v.x);
        c0[nt][3] = aw0*(c0[nt][3] + b0v.y) + aw1*(c1[nt][3] + b1v.y);
    }

    size_t sb0 = tok_to_spatial(t0);
    size_t sb1 = tok_to_spatial(t1);
    #pragma unroll
    for (int nt = 0; nt < 12; nt++) {
        int cch = nt*8 + lq*2;
        c0[nt][0] += x[sb0 + (size_t)cch*SP];
        c0[nt][1] += x[sb0 + (size_t)(cch+1)*SP];
        c0[nt][2] += x[sb1 + (size_t)cch*SP];
        c0[nt][3] += x[sb1 + (size_t)(cch+1)*SP];
    }

    float s0 = 0.f, q0 = 0.f, s1 = 0.f, q1 = 0.f;
    #pragma unroll
    for (int nt = 0; nt < 12; nt++) {
        s0 += c0[nt][0] + c0[nt][1];
        q0 += c0[nt][0]*c0[nt][0] + c0[nt][1]*c0[nt][1];
        s1 += c0[nt][2] + c0[nt][3];
        q1 += c0[nt][2]*c0[nt][2] + c0[nt][3]*c0[nt][3];
    }
    s0 += __shfl_xor_sync(0xffffffffu, s0, 1); s0 += __shfl_xor_sync(0xffffffffu, s0, 2);
    q0 += __shfl_xor_sync(0xffffffffu, q0, 1); q0 += __shfl_xor_sync(0xffffffffu, q0, 2);
    s1 += __shfl_xor_sync(0xffffffffu, s1, 1); s1 += __shfl_xor_sync(0xffffffffu, s1, 2);
    q1 += __shfl_xor_sync(0xffffffffu, q1, 1); q1 += __shfl_xor_sync(0xffffffffu, q1, 2);
    float mu0 = s0 * (1.0f/CB), mu1 = s1 * (1.0f/CB);
    float ri0 = rsqrtf(q0 * (1.0f/CB) - mu0*mu0 + 1e-5f);
    float ri1 = rsqrtf(q1 * (1.0f/CB) - mu1*mu1 + 1e-5f);

    #pragma unroll
    for (int nt = 0; nt < 12; nt++) {
        int cch = nt*8 + lq*2;
        float w0 = lnw[cch], w1 = lnw[cch+1];
        float b0 = lnb[cch], b1 = lnb[cch+1];
        g_x1[sb0 + (size_t)cch*SP]     = c0[nt][0];
        g_x1[sb0 + (size_t)(cch+1)*SP] = c0[nt][1];
        g_x1[sb1 + (size_t)cch*SP]     = c0[nt][2];
        g_x1[sb1 + (size_t)(cch+1)*SP] = c0[nt][3];
        g_x2[sb0 + (size_t)cch*SP]     = to_tf32((c0[nt][0] - mu0)*ri0*w0 + b0);
        g_x2[sb0 + (size_t)(cch+1)*SP] = to_tf32((c0[nt][1] - mu0)*ri0*w1 + b1);
        g_x2[sb1 + (size_t)cch*SP]     = to_tf32((c0[nt][2] - mu1)*ri1*w0 + b0);
        g_x2[sb1 + (size_t)(cch+1)*SP] = to_tf32((c0[nt][3] - mu1)*ri1*w1 + b1);
    }
}

// ---------------- build effective conv weights (NAS fold, tf32-rounded) ------
__global__ void k_weff(const float* __restrict__ c3w, const float* __restrict__ c3b,
                       const float* __restrict__ c1w, const float* __restrict__ c1b,
                       const float* __restrict__ dww, const float* __restrict__ dwb,
                       const float* __restrict__ alpha) {
    float a[4]; float m = -1e30f;
    #pragma unroll
    for (int i = 0; i < 4; i++) { a[i] = alpha[i]; m = fmaxf(m, a[i]); }
    float s = 0.f;
    #pragma unroll
    for (int i = 0; i < 4; i++) { a[i] = __expf(a[i] - m); s += a[i]; }
    float inv = 1.f / s;
    #pragma unroll
    for (int i = 0; i < 4; i++) a[i] *= inv;
    int total = CB*CB*27;
    for (int idx = blockIdx.x*blockDim.x + threadIdx.x; idx < total; idx += gridDim.x*blockDim.x) {
        int t = idx % 27; int rest = idx / 27; int ci = rest % CB; int co = rest / CB;
        float val = a[0] * c3w[idx];
        if (t == 13)            val += a[1] * c1w[co*CB + ci];
        if (ci == co)           val += a[2] * dww[co*27 + t];
        if (t == 13 && ci == co) val += a[3];
        int tt = t / 3, tw = t % 3;
        g_weff[(((size_t)tt*CB + ci)*3 + tw)*CB + co] = to_tf32(val);
    }
    int gid = blockIdx.x*blockDim.x + threadIdx.x;
    if (gid < CB) g_beff[gid] = a[0]*c3b[gid] + a[1]*c1b[gid] + a[2]*dwb[gid];
}

// ---------------- FFN as tf32 implicit-GEMM mma + residual (double-buffered) -
#define KCH 32
#define AST 104
#define BST 232
#define FBUF (KCH*AST + KCH*BST)   // 10752 floats per buffer

__global__ void __launch_bounds__(256) k_ffn_mma(float* __restrict__ out) {
    extern __shared__ float sm[];
    int bid = blockIdx.x;
    int h4 = bid % 14; int t = bid / 14; int d = t & 7; int bb = t >> 3;
    int h0 = h4*4;
    int tid = threadIdx.x;
    int warp = tid >> 5, lane = tid & 31;
    int wm = warp >> 2, wn = warp & 3;
    int lg = lane >> 2, lq = lane & 3;
    int kk = tid >> 3, nlane = tid & 7;

    float acc[3][7][4];
    #pragma unroll
    for (int mt = 0; mt < 3; mt++) {
        int m = wm*48 + mt*16 + lg;
        float b0 = g_beff[m], b8 = g_beff[m + 8];
        #pragma unroll
        for (int nt = 0; nt < 7; nt++) {
            acc[mt][nt][0] = b0; acc[mt][nt][1] = b0;
            acc[mt][nt][2] = b8; acc[mt][nt][3] = b8;
        }
    }

    auto stage = [&](int buf, int kc) {
        float* As = sm + buf*FBUF;
        float* Bs = As + KCH*AST;
        #pragma unroll
        for (int s = 0; s < 12; s++) {
            int i = tid + s*256;
            int k = i / 96, co = i % 96;
            As[k*AST + co] = g_weff[(size_t)(kc*KCH + k)*CB + co];
        }
        int kg = kc*KCH + kk;
        int tt = kg / 288; int r = kg % 288; int ci = r / 3; int tw = r % 3;
        int td = tt / 3, th = tt % 3;
        int sd = d + td - 1;
        bool dok = (unsigned)sd < 8u;
        const float* rowp[4]; bool rok[4];
        #pragma unroll
        for (int hr = 0; hr < 4; hr++) {
            int sh = h0 + hr + th - 1;
            rok[hr] = dok && (unsigned)sh < 56u;
            rowp[hr] = g_x2 + ((size_t)(bb*CB + ci)*DDIM + sd)*HWs + sh*WDIM + (tw - 1);
        }
        float* bdst = Bs + kk*BST;
        #pragma unroll
        for (int j = 0; j < 28; j++) {
            const int hr = (j*8) / 56;
            const int wb = (j*8) % 56;
            int w = wb + nlane;
            bool ok = rok[hr] && ((unsigned)(w + tw - 1) < 56u);
            bdst[j*8 + nlane] = ok ? rowp[hr][w] : 0.f;
        }
    };

    stage(0, 0);
    for (int kc = 0; kc < 81; kc++) {
        __syncthreads();
        if (kc < 80) stage((kc + 1) & 1, kc + 1);
        const float* As = sm + (kc & 1)*FBUF;
        const float* Bs = As + KCH*AST;
        #pragma unroll
        for (int k8 = 0; k8 < 4; k8++) {
            int kb = k8*8;
            unsigned a[3][4];
            #pragma unroll
            for (int mt = 0; mt < 3; mt++) {
                const float* ap = As + (kb + lq)*AST + wm*48 + mt*16 + lg;
                a[mt][0] = __float_as_uint(ap[0]);
                a[mt][1] = __float_as_uint(ap[8]);
                a[mt][2] = __float_as_uint(ap[4*AST]);
                a[mt][3] = __float_as_uint(ap[4*AST + 8]);
            }
            #pragma unroll
            for (int nt = 0; nt < 7; nt++) {
                const float* bp = Bs + (kb + lq)*BST + wn*56 + nt*8 + lg;
                unsigned b0 = __float_as_uint(bp[0]);
                unsigned b1 = __float_as_uint(bp[4*BST]);
                mma_tf32(acc[0][nt], a[0], b0, b1);
                mma_tf32(acc[1][nt], a[1], b0, b1);
                mma_tf32(acc[2][nt], a[2], b0, b1);
            }
        }
    }

    int hrow = h0 + wn;
    #pragma unroll
    for (int mt = 0; mt < 3; mt++) {
        int m = wm*48 + mt*16 + lg;
        size_t base = ((size_t)(bb*CB + m)*DDIM + d)*HWs + hrow*WDIM;
        #pragma unroll
        for (int nt = 0; nt < 7; nt++) {
            int w0 = nt*8 + lq*2;
            size_t i0 = base + w0;
            size_t i1 = i0 + (size_t)8*SP;
            float2 r0 = *(const float2*)(g_x1 + i0);
            float2 r1 = *(const float2*)(g_x1 + i1);
            float2 o0 = make_float2(r0.x + acc[mt][nt][0], r0.y + acc[mt][nt][1]);
            float2 o1 = make_float2(r1.x + acc[mt][nt][2], r1.y + acc[mt][nt][3]);
            *(float2*)(out + i0) = o0;
            *(float2*)(out + i1) = o1;
        }
    }
}

// ---------------- host launch ----------------
extern "C" void kernel_launch(void* const* d_in, const int* in_sizes, int n_in,
                              void* d_out, int out_size) {
    (void)in_sizes; (void)n_in; (void)out_size;
    const float* x      = (const float*)d_in[0];
    const float* ln1w   = (const float*)d_in[1];
    const float* ln1b   = (const float*)d_in[2];
    const float* ln2w   = (const float*)d_in[3];
    const float* ln2b   = (const float*)d_in[4];
    const float* qkvw0  = (const float*)d_in[5];
    const float* qkvb0  = (const float*)d_in[6];
    const float* projw0 = (const float*)d_in[7];
    const float* projb0 = (const float*)d_in[8];
    const float* rpb0   = (const float*)d_in[9];
    const float* qkvw1  = (const float*)d_in[10];
    const float* qkvb1  = (const float*)d_in[11];
    const float* projw1 = (const float*)d_in[12];
    const float* projb1 = (const float*)d_in[13];
    const float* rpb1   = (const float*)d_in[14];
    const float* alphaA = (const float*)d_in[15];
    const float* c3w    = (const float*)d_in[16];
    const float* c3b    = (const float*)d_in[17];
    const float* c1w    = (const float*)d_in[18];
    const float* c1b    = (const float*)d_in[19];
    const float* dww    = (const float*)d_in[20];
    const float* dwb    = (const float*)d_in[21];
    const float* alphaF = (const float*)d_in[22];
    float* out = (float*)d_out;

    float *p_xw, *p_q0, *p_q1, *p_o0, *p_o1;
    cudaGetSymbolAddress((void**)&p_xw, g_xw);
    cudaGetSymbolAddress((void**)&p_q0, g_qkv0);
    cudaGetSymbolAddress((void**)&p_q1, g_qkv1);
    cudaGetSymbolAddress((void**)&p_o0, g_o0);
    cudaGetSymbolAddress((void**)&p_o1, g_o1);

    int smG  = (96*WSTG) * 4;                       // 39936 B
    int smP  = (2*96*WSTG) * 4;                     // 79872 B
    int smA0 = (32*408 + NTP*40 + 12*16*84) * 4;    // 180736 B (12 warps)
    int smA1 = (16*408 + NTP*24 + 8*16*84) * 4;     // 107520 B
    int smF  = 2*FBUF*4;                            // 86016 B
    cudaFuncSetAttribute((const void*)k_gemm_mma,
                         cudaFuncAttributeMaxDynamicSharedMemorySize, smG);
    cudaFuncSetAttribute((const void*)k_projmix,
                         cudaFuncAttributeMaxDynamicSharedMemorySize, smP);
    cudaFuncSetAttribute((const void*)k_attn_mma<32,3,0,1,384>,
                         cudaFuncAttributeMaxDynamicSharedMemorySize, smA0);
    cudaFuncSetAttribute((const void*)k_attn_mma<16,6,3,2,256>,
                         cudaFuncAttributeMaxDynamicSharedMemorySize, smA1);
    cudaFuncSetAttribute((const void*)k_ffn_mma,
                         cudaFuncAttributeMaxDynamicSharedMemorySize, smF);

    // 0) bias+mask table
    k_bias<<<4*9*NTP, NTP>>>(rpb0, rpb1);

    // 1) LN1 + roll + window partition
    k_ln1<<<2*DDIM*HDIM, 256>>>(x, ln1w, ln1b);

    // 2) QKV GEMMs (R10 config: two launches)
    dim3 gq(NTOK/128, 3);
    k_gemm_mma<<<gq, 256, smG>>>(p_xw, qkvw0, qkvb0, p_q0, 288);
    k_gemm_mma<<<gq, 256, smG>>>(p_xw, qkvw1, qkvb1, p_q1, 288);

    // 3) windowed attention (tf32 mma; DH=32 with 12 warps, DH=16 with 8)
    k_attn_mma<32,3,0,1,384><<<NWIN*3, 384, smA0>>>(p_q0, p_o0);
    k_attn_mma<16,6,3,2,256><<<NWIN*6, 256, smA1>>>(p_q1, p_o1);

    // 4) fused proj + mix + reverse + residual + LN2
    k_projmix<<<NTOK/128, 256, smP>>>(p_o0, p_o1, projw0, projb0, projw1, projb1,
                                      ln2w, ln2b, alphaA, x);

    // 5) effective conv weights (tf32) + tensor-core FFN + residual
    k_weff<<<128, 256>>>(c3w, c3b, c1w, c1b, dww, dwb, alphaF);
    k_ffn_mma<<<2*DDIM*(HDIM/4), 256, smF>>>(out);
}

// round 15
// speedup vs baseline: 1.0606x; 1.0208x over previous
#include <cuda_runtime.h>
#include <cstdint>

#define CB 96
#define DDIM 8
#define HDIM 56
#define WDIM 56
#define SP   (DDIM*HDIM*WDIM)   // 25088
#define HWs  (HDIM*WDIM)        // 3136
#define NT   392                // tokens per window
#define NTP  400                // padded tokens
#define NWIN 128                // total windows (B=2, 64 per batch)
#define NTOK (NWIN*NT)          // 50176

__device__ __forceinline__ float to_tf32(float x) {
    unsigned u;
    asm("cvt.rna.tf32.f32 %0, %1;" : "=r"(u) : "f"(x));
    return __uint_as_float(u);
}

__device__ __forceinline__ void mma_tf32(float* c, const unsigned* a, unsigned b0, unsigned b1) {
    asm volatile(
        "mma.sync.aligned.m16n8k8.row.col.f32.tf32.tf32.f32 "
        "{%0,%1,%2,%3}, {%4,%5,%6,%7}, {%8,%9}, {%0,%1,%2,%3};\n"
        : "+f"(c[0]), "+f"(c[1]), "+f"(c[2]), "+f"(c[3])
        : "r"(a[0]), "r"(a[1]), "r"(a[2]), "r"(a[3]), "r"(b0), "r"(b1));
}

// token id -> spatial base offset (window reverse + un-roll), channel 0
__device__ __forceinline__ size_t tok_to_spatial(int t) {
    int win = t / NT, n = t % NT;
    int bb = win >> 6; int whi = (win & 63) >> 3, wwi = win & 7;
    int dz = n/49, r = n%49, hy = r/7, wl = r%7;
    int hs = whi*7 + hy, ws = wwi*7 + wl;
    int d0 = (dz + 4) & 7;
    int h0 = hs + 3; if (h0 >= HDIM) h0 -= HDIM;
    int w0 = ws + 3; if (w0 >= WDIM) w0 -= WDIM;
    return (size_t)bb*CB*SP + (size_t)d0*HWs + h0*WDIM + w0;
}

// ---------------- scratch (device globals; no allocation) ----------------
__device__ float g_xw  [NTOK*CB];
__device__ float g_qkv0[NTOK*288];
__device__ float g_qkv1[NTOK*288];
__device__ float g_o0  [NTOK*CB];
__device__ float g_o1  [NTOK*CB];
__device__ float g_x1  [2*CB*SP];
__device__ float g_x2  [2*CB*SP];     // LN2(x1), tf32-rounded
__device__ float g_weff[9*CB*3*CB];   // [k][co], tf32-rounded
__device__ float g_beff[CB];
__device__ float g_bias[4*9*NTP*NTP]; // [class][head9][i][j]

// ---------------- LN1 + shift-roll + window partition (v2) ----------------
__global__ void k_ln1(const float* __restrict__ x,
                      const float* __restrict__ lw, const float* __restrict__ lb) {
    __shared__ float row[WDIM*97];
    __shared__ float s_mu[WDIM], s_ri[WDIM];
    int bid = blockIdx.x;
    int h = bid % HDIM; int t = bid / HDIM; int d = t & 7; int bb = t >> 3;
    const float* base = x + (size_t)bb*CB*SP + d*HWs + h*WDIM;
    for (int i = threadIdx.x; i < CB*WDIM; i += 256) {
        int c = i / WDIM, w = i % WDIM;
        row[w*97 + c] = base[(size_t)c*SP + w];
    }
    __syncthreads();
    if (threadIdx.x < 4*WDIM) {
        int w = threadIdx.x >> 2, part = threadIdx.x & 3;
        float s = 0.f, s2 = 0.f;
        const float* rp = row + w*97 + part*24;
        #pragma unroll 6
        for (int k = 0; k < 24; k++) { float v = rp[k]; s += v; s2 += v*v; }
        s  += __shfl_xor_sync(0xffffffffu, s, 1);  s  += __shfl_xor_sync(0xffffffffu, s, 2);
        s2 += __shfl_xor_sync(0xffffffffu, s2, 1); s2 += __shfl_xor_sync(0xffffffffu, s2, 2);
        if (part == 0) {
            float mu = s * (1.0f/CB);
            s_mu[w] = mu;
            s_ri[w] = rsqrtf(s2 * (1.0f/CB) - mu*mu + 1e-5f);
        }
    }
    __syncthreads();
    int ds = (d + 4) & 7;
    for (int i = threadIdx.x; i < CB*WDIM; i += 256) {
        int w = i / CB, c = i % CB;
        int hs = h - 3; if (hs < 0) hs += HDIM;
        int ws = w - 3; if (ws < 0) ws += WDIM;
        int win = bb*64 + (hs/7)*8 + (ws/7);
        int n   = ds*49 + (hs%7)*7 + (ws%7);
        g_xw[((size_t)win*NT + n)*CB + c] =
            (row[w*97 + c] - s_mu[w]) * s_ri[w] * lw[c] + lb[c];
    }
}

// ---------------- GEMM via tf32 mma (A direct from global) ------
#define WSTG 104   // Ws [k][n] stride
__global__ void __launch_bounds__(256) k_gemm_mma(const float* __restrict__ A,
                                                  const float* __restrict__ W,
                                                  const float* __restrict__ bias,
                                                  float* __restrict__ Out, int Ntot) {
    extern __shared__ float sm[];
    float* Ws = sm;                 // 96*WSTG
    int m0 = blockIdx.x * 128;
    int n0 = blockIdx.y * 96;
    int tid = threadIdx.x, warp = tid >> 5, lane = tid & 31;
    int lg = lane >> 2, lq = lane & 3;

    for (int i = tid; i < 96*24; i += 256) {
        int n = i / 24, c4 = i % 24;
        float4 v = *(const float4*)(W + (size_t)(n0 + n)*CB + c4*4);
        Ws[(c4*4+0)*WSTG + n] = to_tf32(v.x);
        Ws[(c4*4+1)*WSTG + n] = to_tf32(v.y);
        Ws[(c4*4+2)*WSTG + n] = to_tf32(v.z);
        Ws[(c4*4+3)*WSTG + n] = to_tf32(v.w);
    }
    __syncthreads();

    float c[12][4];
    #pragma unroll
    for (int nt = 0; nt < 12; nt++) { c[nt][0]=0.f; c[nt][1]=0.f; c[nt][2]=0.f; c[nt][3]=0.f; }

    int r0 = m0 + warp*16 + lg;
    const float* ap0 = A + (size_t)r0*CB + lq;
    const float* ap1 = ap0 + 8*CB;
    #pragma unroll
    for (int ks = 0; ks < 12; ks++) {
        int kb = ks*8;
        unsigned a[4];
        a[0] = __float_as_uint(to_tf32(ap0[kb]));
        a[1] = __float_as_uint(to_tf32(ap1[kb]));
        a[2] = __float_as_uint(to_tf32(ap0[kb + 4]));
        a[3] = __float_as_uint(to_tf32(ap1[kb + 4]));
        #pragma unroll
        for (int nt = 0; nt < 12; nt++) {
            const float* bp = Ws + (kb + lq)*WSTG + nt*8 + lg;
            unsigned b0 = __float_as_uint(bp[0]);
            unsigned b1 = __float_as_uint(bp[4*WSTG]);
            mma_tf32(c[nt], a, b0, b1);
        }
    }

    #pragma unroll
    for (int nt = 0; nt < 12; nt++) {
        int nc = n0 + nt*8 + lq*2;
        float2 bv = *(const float2*)(bias + nc);
        *(float2*)(Out + (size_t)r0*Ntot + nc)
            = make_float2(c[nt][0] + bv.x, c[nt][1] + bv.y);
        *(float2*)(Out + (size_t)(r0 + 8)*Ntot + nc)
            = make_float2(c[nt][2] + bv.x, c[nt][3] + bv.y);
    }
}

// ---------------- bias+mask table precompute ----------------
__global__ void k_bias(const float* __restrict__ rpb0, const float* __restrict__ rpb1) {
    int bid = blockIdx.x;
    int i = bid % NTP; int rest = bid / NTP;
    int head = rest % 9; int cls = rest / 9;
    int j = threadIdx.x;
    float v;
    if (i >= NT || j >= NT) {
        v = -1e9f;
    } else {
        int dzi = i/49, ri = i%49, hyi = ri/7, wli = ri%7;
        int dzj = j/49, rj = j%49, hyj = rj/7, wlj = rj%7;
        int idx = (dzi - dzj + 7)*169 + (hyi - hyj + 6)*13 + (wli - wlj + 6);
        float b = (head < 3) ? rpb0[idx*3 + head] : rpb1[idx*6 + head - 3];
        int ha = cls >> 1, wa = cls & 1;
        int hri = ha ? (hyi < 4 ? 1 : 2) : 0;
        int wri = wa ? (wli < 4 ? 1 : 2) : 0;
        int hrj = ha ? (hyj < 4 ? 1 : 2) : 0;
        int wrj = wa ? (wlj < 4 ? 1 : 2) : 0;
        int li = (dzi < 4 ? 0 : 1)*9 + hri*3 + wri;
        int lj = (dzj < 4 ? 0 : 1)*9 + hrj*3 + wrj;
        v = b + ((li != lj) ? -100.f : 0.f);
    }
    g_bias[((size_t)(cls*9 + head)*NTP + i)*NTP + j] = v;
}

// ---------------- windowed attention: tf32 mma + flash softmax ---------------
template<int DH, int NH, int HOFF, int MAXB, int NTHR>
__global__ void __launch_bounds__(NTHR, MAXB) k_attn_mma(const float* __restrict__ qkv,
                                                         float* __restrict__ outp) {
    constexpr int NW  = NTHR/32;
    constexpr int KST = 408;
    constexpr int VST = (DH == 32) ? 40 : 24;
    constexpr int PST = 84;
    constexpr int NKS = DH/8;
    constexpr int NVT = DH/8;
    extern __shared__ float sm[];
    float* Ksm = sm;
    float* Vsm = Ksm + DH*KST;
    float* Psm = Vsm + NTP*VST;

    int win = blockIdx.x / NH, hd = blockIdx.x % NH;
    const float* qb = qkv + (size_t)win*NT*288;
    int tid = threadIdx.x, warp = tid >> 5, lane = tid & 31;
    int lg = lane >> 2, lq = lane & 3;
    const float scale = rsqrtf((float)DH);

    for (int idx = tid; idx < NTP*(DH/4); idx += NTHR) {
        int n = idx / (DH/4), d4 = (idx % (DH/4))*4;
        if (n < NT) {
            float4 kv = *(const float4*)(qb + (size_t)n*288 + 96 + hd*DH + d4);
            Ksm[(d4+0)*KST + n] = to_tf32(kv.x);
            Ksm[(d4+1)*KST + n] = to_tf32(kv.y);
            Ksm[(d4+2)*KST + n] = to_tf32(kv.z);
            Ksm[(d4+3)*KST + n] = to_tf32(kv.w);
        } else {
            Ksm[(d4+0)*KST + n] = 0.f;
            Ksm[(d4+1)*KST + n] = 0.f;
            Ksm[(d4+2)*KST + n] = 0.f;
            Ksm[(d4+3)*KST + n] = 0.f;
        }
    }
    for (int idx = tid; idx < NTP*(DH/4); idx += NTHR) {
        int j = idx / (DH/4), d4 = (idx % (DH/4))*4;
        float4 vv = make_float4(0.f, 0.f, 0.f, 0.f);
        if (j < NT) {
            float4 t4 = *(const float4*)(qb + (size_t)j*288 + 192 + hd*DH + d4);
            vv = make_float4(to_tf32(t4.x), to_tf32(t4.y), to_tf32(t4.z), to_tf32(t4.w));
        }
        *(float4*)(Vsm + j*VST + d4) = vv;
    }
    __syncthreads();

    int cls = ((((win & 63) >> 3) == 7) ? 2 : 0) | (((win & 7) == 7) ? 1 : 0);
    const float* bias = g_bias + (size_t)(cls*9 + HOFF + hd)*(NTP*NTP);
    float* pwarp = Psm + warp*(16*PST);

    for (int tr = warp; tr < 25; tr += NW) {
        int i0 = tr*16;
        int r0 = i0 + lg;
        int r1 = min(i0 + lg + 8, NT - 1);
        unsigned qa[NKS][4];
        #pragma unroll
        for (int ks = 0; ks < NKS; ks++) {
            int d = ks*8 + lq;
            qa[ks][0] = __float_as_uint(to_tf32(qb[(size_t)r0*288 + hd*DH + d]     * scale));
            qa[ks][1] = __float_as_uint(to_tf32(qb[(size_t)r1*288 + hd*DH + d]     * scale));
            qa[ks][2] = __float_as_uint(to_tf32(qb[(size_t)r0*288 + hd*DH + d + 4] * scale));
            qa[ks][3] = __float_as_uint(to_tf32(qb[(size_t)r1*288 + hd*DH + d + 4] * scale));
        }
        float m0 = -1e30f, m1 = -1e30f, l0 = 0.f, l1 = 0.f;
        float O[NVT][4];
        #pragma unroll
        for (int nt = 0; nt < NVT; nt++) { O[nt][0]=0.f; O[nt][1]=0.f; O[nt][2]=0.f; O[nt][3]=0.f; }

        #pragma unroll
        for (int ch = 0; ch < 5; ch++) {
            int j0 = ch*80;
            float c[10][4];
            #pragma unroll
            for (int nt = 0; nt < 10; nt++) { c[nt][0]=0.f; c[nt][1]=0.f; c[nt][2]=0.f; c[nt][3]=0.f; }
            #pragma unroll
            for (int ks = 0; ks < NKS; ks++) {
                #pragma unroll
                for (int nt = 0; nt < 10; nt++) {
                    const float* bp = Ksm + (ks*8 + lq)*KST + j0 + nt*8 + lg;
                    unsigned b0 = __float_as_uint(bp[0]);
                    unsigned b1 = __float_as_uint(bp[4*KST]);
                    mma_tf32(c[nt], qa[ks], b0, b1);
                }
            }
            #pragma unroll
            for (int nt = 0; nt < 10; nt++) {
                const float* br0 = bias + (size_t)(i0 + lg)*NTP + j0 + nt*8 + lq*2;
                float2 b0v = *(const float2*)br0;
                float2 b1v = *(const float2*)(br0 + 8*NTP);
                c[nt][0] += b0v.x; c[nt][1] += b0v.y;
                c[nt][2] += b1v.x; c[nt][3] += b1v.y;
            }
            float cm0 = -1e30f, cm1 = -1e30f;
            #pragma unroll
            for (int nt = 0; nt < 10; nt++) {
                cm0 = fmaxf(cm0, fmaxf(c[nt][0], c[nt][1]));
                cm1 = fmaxf(cm1, fmaxf(c[nt][2], c[nt][3]));
            }
            cm0 = fmaxf(cm0, __shfl_xor_sync(0xffffffffu, cm0, 1));
            cm0 = fmaxf(cm0, __shfl_xor_sync(0xffffffffu, cm0, 2));
            cm1 = fmaxf(cm1, __shfl_xor_sync(0xffffffffu, cm1, 1));
            cm1 = fmaxf(cm1, __shfl_xor_sync(0xffffffffu, cm1, 2));
            float mn0 = fmaxf(m0, cm0), mn1 = fmaxf(m1, cm1);
            float s0 = __expf(m0 - mn0), s1 = __expf(m1 - mn1);
            m0 = mn0; m1 = mn1;
            l0 *= s0; l1 *= s1;
            #pragma unroll
            for (int nt = 0; nt < NVT; nt++) {
                O[nt][0] *= s0; O[nt][1] *= s0;
                O[nt][2] *= s1; O[nt][3] *= s1;
            }
            float sum0 = 0.f, sum1 = 0.f;
            #pragma unroll
            for (int nt = 0; nt < 10; nt++) {
                c[nt][0] = to_tf32(__expf(c[nt][0] - m0)); sum0 += c[nt][0];
                c[nt][1] = to_tf32(__expf(c[nt][1] - m0)); sum0 += c[nt][1];
                c[nt][2] = to_tf32(__expf(c[nt][2] - m1)); sum1 += c[nt][2];
                c[nt][3] = to_tf32(__expf(c[nt][3] - m1)); sum1 += c[nt][3];
            }
            sum0 += __shfl_xor_sync(0xffffffffu, sum0, 1);
            sum0 += __shfl_xor_sync(0xffffffffu, sum0, 2);
            sum1 += __shfl_xor_sync(0xffffffffu, sum1, 1);
            sum1 += __shfl_xor_sync(0xffffffffu, sum1, 2);
            l0 += sum0; l1 += sum1;
            #pragma unroll
            for (int nt = 0; nt < 10; nt++) {
                int jl = nt*8 + lq*2;
                *(float2*)(pwarp + lg*PST + jl)     = make_float2(c[nt][0], c[nt][1]);
                *(float2*)(pwarp + (lg+8)*PST + jl) = make_float2(c[nt][2], c[nt][3]);
            }
            __syncwarp();
            #pragma unroll
            for (int ks = 0; ks < 10; ks++) {
                unsigned pa[4];
                const float* pp = pwarp + lg*PST + ks*8 + lq;
                pa[0] = __float_as_uint(pp[0]);
                pa[1] = __float_as_uint(pp[8*PST]);
                pa[2] = __float_as_uint(pp[4]);
                pa[3] = __float_as_uint(pp[8*PST + 4]);
                #pragma unroll
                for (int nt = 0; nt < NVT; nt++) {
                    const float* vp = Vsm + (j0 + ks*8 + lq)*VST + nt*8 + lg;
                    unsigned b0 = __float_as_uint(vp[0]);
                    unsigned b1 = __float_as_uint(vp[4*VST]);
                    mma_tf32(O[nt], pa, b0, b1);
                }
            }
            __syncwarp();
        }
        float li0 = 1.f / l0, li1 = 1.f / l1;
        int ir0 = i0 + lg, ir1 = i0 + lg + 8;
        #pragma unroll
        for (int nt = 0; nt < NVT; nt++) {
            *(float2*)(outp + ((size_t)win*NT + ir0)*CB + hd*DH + nt*8 + lq*2)
                = make_float2(O[nt][0]*li0, O[nt][1]*li0);
            if (ir1 < NT)
                *(float2*)(outp + ((size_t)win*NT + ir1)*CB + hd*DH + nt*8 + lq*2)
                    = make_float2(O[nt][2]*li1, O[nt][3]*li1);
        }
    }
}

// ---------------- fused proj0+proj1 + NAS mix + reverse + residual + LN2 -----
__global__ void __launch_bounds__(256) k_projmix(
    const float* __restrict__ o0, const float* __restrict__ o1,
    const float* __restrict__ pw0, const float* __restrict__ pb0,
    const float* __restrict__ pw1, const float* __restrict__ pb1,
    const float* __restrict__ lnw, const float* __restrict__ lnb,
    const float* __restrict__ alpha, const float* __restrict__ x) {
    extern __shared__ float sm[];
    float* Ws0 = sm;                 // 96*WSTG
    float* Ws1 = sm + 96*WSTG;
    int m0 = blockIdx.x * 128;
    int tid = threadIdx.x, warp = tid >> 5, lane = tid & 31;
    int lg = lane >> 2, lq = lane & 3;

    for (int i = tid; i < 96*24; i += 256) {
        int n = i / 24, c4 = i % 24;
        float4 v0 = *(const float4*)(pw0 + (size_t)n*CB + c4*4);
        Ws0[(c4*4+0)*WSTG + n] = to_tf32(v0.x);
        Ws0[(c4*4+1)*WSTG + n] = to_tf32(v0.y);
        Ws0[(c4*4+2)*WSTG + n] = to_tf32(v0.z);
        Ws0[(c4*4+3)*WSTG + n] = to_tf32(v0.w);
        float4 v1 = *(const float4*)(pw1 + (size_t)n*CB + c4*4);
        Ws1[(c4*4+0)*WSTG + n] = to_tf32(v1.x);
        Ws1[(c4*4+1)*WSTG + n] = to_tf32(v1.y);
        Ws1[(c4*4+2)*WSTG + n] = to_tf32(v1.z);
        Ws1[(c4*4+3)*WSTG + n] = to_tf32(v1.w);
    }
    __syncthreads();

    float c0[12][4], c1[12][4];
    #pragma unroll
    for (int nt = 0; nt < 12; nt++) {
        c0[nt][0]=0.f; c0[nt][1]=0.f; c0[nt][2]=0.f; c0[nt][3]=0.f;
        c1[nt][0]=0.f; c1[nt][1]=0.f; c1[nt][2]=0.f; c1[nt][3]=0.f;
    }

    int t0 = m0 + warp*16 + lg, t1 = t0 + 8;
    const float* a00 = o0 + (size_t)t0*CB + lq;
    const float* a01 = o0 + (size_t)t1*CB + lq;
    const float* a10 = o1 + (size_t)t0*CB + lq;
    const float* a11 = o1 + (size_t)t1*CB + lq;
    #pragma unroll
    for (int ks = 0; ks < 12; ks++) {
        int kb = ks*8;
        unsigned aA[4], aB[4];
        aA[0] = __float_as_uint(to_tf32(a00[kb]));
        aA[1] = __float_as_uint(to_tf32(a01[kb]));
        aA[2] = __float_as_uint(to_tf32(a00[kb + 4]));
        aA[3] = __float_as_uint(to_tf32(a01[kb + 4]));
        aB[0] = __float_as_uint(to_tf32(a10[kb]));
        aB[1] = __float_as_uint(to_tf32(a11[kb]));
        aB[2] = __float_as_uint(to_tf32(a10[kb + 4]));
        aB[3] = __float_as_uint(to_tf32(a11[kb + 4]));
        #pragma unroll
        for (int nt = 0; nt < 12; nt++) {
            const float* bp0 = Ws0 + (kb + lq)*WSTG + nt*8 + lg;
            mma_tf32(c0[nt], aA, __float_as_uint(bp0[0]), __float_as_uint(bp0[4*WSTG]));
            const float* bp1 = Ws1 + (kb + lq)*WSTG + nt*8 + lg;
            mma_tf32(c1[nt], aB, __float_as_uint(bp1[0]), __float_as_uint(bp1[4*WSTG]));
        }
    }

    float al0 = alpha[0], al1 = alpha[1];
    float am = fmaxf(al0, al1);
    float e0 = __expf(al0 - am), e1 = __expf(al1 - am);
    float ai = 1.f / (e0 + e1);
    float aw0 = e0*ai, aw1 = e1*ai;

    #pragma unroll
    for (int nt = 0; nt < 12; nt++) {
        int cch = nt*8 + lq*2;
        float2 b0v = *(const float2*)(pb0 + cch);
        float2 b1v = *(const float2*)(pb1 + cch);
        c0[nt][0] = aw0*(c0[nt][0] + b0v.x) + aw1*(c1[nt][0] + b1v.x);
        c0[nt][1] = aw0*(c0[nt][1] + b0v.y) + aw1*(c1[nt][1] + b1v.y);
        c0[nt][2] = aw0*(c0[nt][2] + b0v.x) + aw1*(c1[nt][2] + b1v.x);
        c0[nt][3] = aw0*(c0[nt][3] + b0v.y) + aw1*(c1[nt][3] + b1v.y);
    }

    size_t sb0 = tok_to_spatial(t0);
    size_t sb1 = tok_to_spatial(t1);
    #pragma unroll
    for (int nt = 0; nt < 12; nt++) {
        int cch = nt*8 + lq*2;
        c0[nt][0] += x[sb0 + (size_t)cch*SP];
        c0[nt][1] += x[sb0 + (size_t)(cch+1)*SP];
        c0[nt][2] += x[sb1 + (size_t)cch*SP];
        c0[nt][3] += x[sb1 + (size_t)(cch+1)*SP];
    }

    float s0 = 0.f, q0 = 0.f, s1 = 0.f, q1 = 0.f;
    #pragma unroll
    for (int nt = 0; nt < 12; nt++) {
        s0 += c0[nt][0] + c0[nt][1];
        q0 += c0[nt][0]*c0[nt][0] + c0[nt][1]*c0[nt][1];
        s1 += c0[nt][2] + c0[nt][3];
        q1 += c0[nt][2]*c0[nt][2] + c0[nt][3]*c0[nt][3];
    }
    s0 += __shfl_xor_sync(0xffffffffu, s0, 1); s0 += __shfl_xor_sync(0xffffffffu, s0, 2);
    q0 += __shfl_xor_sync(0xffffffffu, q0, 1); q0 += __shfl_xor_sync(0xffffffffu, q0, 2);
    s1 += __shfl_xor_sync(0xffffffffu, s1, 1); s1 += __shfl_xor_sync(0xffffffffu, s1, 2);
    q1 += __shfl_xor_sync(0xffffffffu, q1, 1); q1 += __shfl_xor_sync(0xffffffffu, q1, 2);
    float mu0 = s0 * (1.0f/CB), mu1 = s1 * (1.0f/CB);
    float ri0 = rsqrtf(q0 * (1.0f/CB) - mu0*mu0 + 1e-5f);
    float ri1 = rsqrtf(q1 * (1.0f/CB) - mu1*mu1 + 1e-5f);

    #pragma unroll
    for (int nt = 0; nt < 12; nt++) {
        int cch = nt*8 + lq*2;
        float w0 = lnw[cch], w1 = lnw[cch+1];
        float b0 = lnb[cch], b1 = lnb[cch+1];
        g_x1[sb0 + (size_t)cch*SP]     = c0[nt][0];
        g_x1[sb0 + (size_t)(cch+1)*SP] = c0[nt][1];
        g_x1[sb1 + (size_t)cch*SP]     = c0[nt][2];
        g_x1[sb1 + (size_t)(cch+1)*SP] = c0[nt][3];
        g_x2[sb0 + (size_t)cch*SP]     = to_tf32((c0[nt][0] - mu0)*ri0*w0 + b0);
        g_x2[sb0 + (size_t)(cch+1)*SP] = to_tf32((c0[nt][1] - mu0)*ri0*w1 + b1);
        g_x2[sb1 + (size_t)cch*SP]     = to_tf32((c0[nt][2] - mu1)*ri1*w0 + b0);
        g_x2[sb1 + (size_t)(cch+1)*SP] = to_tf32((c0[nt][3] - mu1)*ri1*w1 + b1);
    }
}

// ---------------- build effective conv weights (NAS fold, tf32-rounded) ------
__global__ void k_weff(const float* __restrict__ c3w, const float* __restrict__ c3b,
                       const float* __restrict__ c1w, const float* __restrict__ c1b,
                       const float* __restrict__ dww, const float* __restrict__ dwb,
                       const float* __restrict__ alpha) {
    float a[4]; float m = -1e30f;
    #pragma unroll
    for (int i = 0; i < 4; i++) { a[i] = alpha[i]; m = fmaxf(m, a[i]); }
    float s = 0.f;
    #pragma unroll
    for (int i = 0; i < 4; i++) { a[i] = __expf(a[i] - m); s += a[i]; }
    float inv = 1.f / s;
    #pragma unroll
    for (int i = 0; i < 4; i++) a[i] *= inv;
    int total = CB*CB*27;
    for (int idx = blockIdx.x*blockDim.x + threadIdx.x; idx < total; idx += gridDim.x*blockDim.x) {
        int t = idx % 27; int rest = idx / 27; int ci = rest % CB; int co = rest / CB;
        float val = a[0] * c3w[idx];
        if (t == 13)            val += a[1] * c1w[co*CB + ci];
        if (ci == co)           val += a[2] * dww[co*27 + t];
        if (t == 13 && ci == co) val += a[3];
        int tt = t / 3, tw = t % 3;
        g_weff[(((size_t)tt*CB + ci)*3 + tw)*CB + co] = to_tf32(val);
    }
    int gid = blockIdx.x*blockDim.x + threadIdx.x;
    if (gid < CB) g_beff[gid] = a[0]*c3b[gid] + a[1]*c1b[gid] + a[2]*dwb[gid];
}

// ---------------- FFN as tf32 implicit-GEMM mma + residual (double-buffered) -
#define KCH 32
#define AST 104
#define BST 232
#define FBUF (KCH*AST + KCH*BST)   // 10752 floats per buffer

__global__ void __launch_bounds__(256) k_ffn_mma(float* __restrict__ out) {
    extern __shared__ float sm[];
    int bid = blockIdx.x;
    int h4 = bid % 14; int t = bid / 14; int d = t & 7; int bb = t >> 3;
    int h0 = h4*4;
    int tid = threadIdx.x;
    int warp = tid >> 5, lane = tid & 31;
    int wm = warp >> 2, wn = warp & 3;
    int lg = lane >> 2, lq = lane & 3;
    int kk = tid >> 3, nlane = tid & 7;

    float acc[3][7][4];
    #pragma unroll
    for (int mt = 0; mt < 3; mt++) {
        int m = wm*48 + mt*16 + lg;
        float b0 = g_beff[m], b8 = g_beff[m + 8];
        #pragma unroll
        for (int nt = 0; nt < 7; nt++) {
            acc[mt][nt][0] = b0; acc[mt][nt][1] = b0;
            acc[mt][nt][2] = b8; acc[mt][nt][3] = b8;
        }
    }

    auto stage = [&](int buf, int kc) {
        float* As = sm + buf*FBUF;
        float* Bs = As + KCH*AST;
        #pragma unroll
        for (int s = 0; s < 12; s++) {
            int i = tid + s*256;
            int k = i / 96, co = i % 96;
            As[k*AST + co] = g_weff[(size_t)(kc*KCH + k)*CB + co];
        }
        int kg = kc*KCH + kk;
        int tt = kg / 288; int r = kg % 288; int ci = r / 3; int tw = r % 3;
        int td = tt / 3, th = tt % 3;
        int sd = d + td - 1;
        bool dok = (unsigned)sd < 8u;
        const float* rowp[4]; bool rok[4];
        #pragma unroll
        for (int hr = 0; hr < 4; hr++) {
            int sh = h0 + hr + th - 1;
            rok[hr] = dok && (unsigned)sh < 56u;
            rowp[hr] = g_x2 + ((size_t)(bb*CB + ci)*DDIM + sd)*HWs + sh*WDIM + (tw - 1);
        }
        float* bdst = Bs + kk*BST;
        #pragma unroll
        for (int j = 0; j < 28; j++) {
            const int hr = (j*8) / 56;
            const int wb = (j*8) % 56;
            int w = wb + nlane;
            bool ok = rok[hr] && ((unsigned)(w + tw - 1) < 56u);
            bdst[j*8 + nlane] = ok ? rowp[hr][w] : 0.f;
        }
    };

    stage(0, 0);
    for (int kc = 0; kc < 81; kc++) {
        __syncthreads();
        if (kc < 80) stage((kc + 1) & 1, kc + 1);
        const float* As = sm + (kc & 1)*FBUF;
        const float* Bs = As + KCH*AST;
        #pragma unroll
        for (int k8 = 0; k8 < 4; k8++) {
            int kb = k8*8;
            unsigned a[3][4];
            #pragma unroll
            for (int mt = 0; mt < 3; mt++) {
                const float* ap = As + (kb + lq)*AST + wm*48 + mt*16 + lg;
                a[mt][0] = __float_as_uint(ap[0]);
                a[mt][1] = __float_as_uint(ap[8]);
                a[mt][2] = __float_as_uint(ap[4*AST]);
                a[mt][3] = __float_as_uint(ap[4*AST + 8]);
            }
            #pragma unroll
            for (int nt = 0; nt < 7; nt++) {
                const float* bp = Bs + (kb + lq)*BST + wn*56 + nt*8 + lg;
                unsigned b0 = __float_as_uint(bp[0]);
                unsigned b1 = __float_as_uint(bp[4*BST]);
                mma_tf32(acc[0][nt], a[0], b0, b1);
                mma_tf32(acc[1][nt], a[1], b0, b1);
                mma_tf32(acc[2][nt], a[2], b0, b1);
            }
        }
    }

    int hrow = h0 + wn;
    #pragma unroll
    for (int mt = 0; mt < 3; mt++) {
        int m = wm*48 + mt*16 + lg;
        size_t base = ((size_t)(bb*CB + m)*DDIM + d)*HWs + hrow*WDIM;
        #pragma unroll
        for (int nt = 0; nt < 7; nt++) {
            int w0 = nt*8 + lq*2;
            size_t i0 = base + w0;
            size_t i1 = i0 + (size_t)8*SP;
            float2 r0 = *(const float2*)(g_x1 + i0);
            float2 r1 = *(const float2*)(g_x1 + i1);
            float2 o0 = make_float2(r0.x + acc[mt][nt][0], r0.y + acc[mt][nt][1]);
            float2 o1 = make_float2(r1.x + acc[mt][nt][2], r1.y + acc[mt][nt][3]);
            *(float2*)(out + i0) = o0;
            *(float2*)(out + i1) = o1;
        }
    }
}

// ---------------- host launch (two-stream fork/join inside capture) ----------
extern "C" void kernel_launch(void* const* d_in, const int* in_sizes, int n_in,
                              void* d_out, int out_size) {
    (void)in_sizes; (void)n_in; (void)out_size;
    const float* x      = (const float*)d_in[0];
    const float* ln1w   = (const float*)d_in[1];
    const float* ln1b   = (const float*)d_in[2];
    const float* ln2w   = (const float*)d_in[3];
    const float* ln2b   = (const float*)d_in[4];
    const float* qkvw0  = (const float*)d_in[5];
    const float* qkvb0  = (const float*)d_in[6];
    const float* projw0 = (const float*)d_in[7];
    const float* projb0 = (const float*)d_in[8];
    const float* rpb0   = (const float*)d_in[9];
    const float* qkvw1  = (const float*)d_in[10];
    const float* qkvb1  = (const float*)d_in[11];
    const float* projw1 = (const float*)d_in[12];
    const float* projb1 = (const float*)d_in[13];
    const float* rpb1   = (const float*)d_in[14];
    const float* alphaA = (const float*)d_in[15];
    const float* c3w    = (const float*)d_in[16];
    const float* c3b    = (const float*)d_in[17];
    const float* c1w    = (const float*)d_in[18];
    const float* c1b    = (const float*)d_in[19];
    const float* dww    = (const float*)d_in[20];
    const float* dwb    = (const float*)d_in[21];
    const float* alphaF = (const float*)d_in[22];
    float* out = (float*)d_out;

    float *p_xw, *p_q0, *p_q1, *p_o0, *p_o1;
    cudaGetSymbolAddress((void**)&p_xw, g_xw);
    cudaGetSymbolAddress((void**)&p_q0, g_qkv0);
    cudaGetSymbolAddress((void**)&p_q1, g_qkv1);
    cudaGetSymbolAddress((void**)&p_o0, g_o0);
    cudaGetSymbolAddress((void**)&p_o1, g_o1);

    int smG  = (96*WSTG) * 4;                       // 39936 B
    int smP  = (2*96*WSTG) * 4;                     // 79872 B
    int smA0 = (32*408 + NTP*40 + 12*16*84) * 4;    // 180736 B (12 warps)
    int smA1 = (16*408 + NTP*24 + 8*16*84) * 4;     // 107520 B
    int smF  = 2*FBUF*4;                            // 86016 B
    cudaFuncSetAttribute((const void*)k_gemm_mma,
                         cudaFuncAttributeMaxDynamicSharedMemorySize, smG);
    cudaFuncSetAttribute((const void*)k_projmix,
                         cudaFuncAttributeMaxDynamicSharedMemorySize, smP);
    cudaFuncSetAttribute((const void*)k_attn_mma<32,3,0,1,384>,
                         cudaFuncAttributeMaxDynamicSharedMemorySize, smA0);
    cudaFuncSetAttribute((const void*)k_attn_mma<16,6,3,2,256>,
                         cudaFuncAttributeMaxDynamicSharedMemorySize, smA1);
    cudaFuncSetAttribute((const void*)k_ffn_mma,
                         cudaFuncAttributeMaxDynamicSharedMemorySize, smF);

    // side stream + events: created once, outside capture (first call is the
    // uncaptured correctness run). Work launched is identical on every call.
    static cudaStream_t s2 = nullptr;
    static cudaEvent_t  eFork = nullptr, eJoin = nullptr;
    if (s2 == nullptr) {
        cudaStreamCreateWithFlags(&s2, cudaStreamNonBlocking);
        cudaEventCreateWithFlags(&eFork, cudaEventDisableTiming);
        cudaEventCreateWithFlags(&eJoin, cudaEventDisableTiming);
    }

    // ---- default stream: prerequisites for both branches ----
    k_bias<<<4*9*NTP, NTP>>>(rpb0, rpb1);
    k_ln1<<<2*DDIM*HDIM, 256>>>(x, ln1w, ln1b);
    cudaEventRecord(eFork, 0);

    // ---- branch 1 on s2: weff + qkv1 + attn1 ----
    cudaStreamWaitEvent(s2, eFork, 0);
    k_weff<<<128, 256, 0, s2>>>(c3w, c3b, c1w, c1b, dww, dwb, alphaF);
    dim3 gq(NTOK/128, 3);
    k_gemm_mma<<<gq, 256, smG, s2>>>(p_xw, qkvw1, qkvb1, p_q1, 288);
    k_attn_mma<16,6,3,2,256><<<NWIN*6, 256, smA1, s2>>>(p_q1, p_o1);
    cudaEventRecord(eJoin, s2);

    // ---- branch 0 on default: qkv0 + attn0 ----
    k_gemm_mma<<<gq, 256, smG>>>(p_xw, qkvw0, qkvb0, p_q0, 288);
    k_attn_mma<32,3,0,1,384><<<NWIN*3, 384, smA0>>>(p_q0, p_o0);

    // ---- join, then tail ----
    cudaStreamWaitEvent(0, eJoin, 0);
    k_projmix<<<NTOK/128, 256, smP>>>(p_o0, p_o1, projw0, projb0, projw1, projb1,
                                      ln2w, ln2b, alphaA, x);
    k_ffn_mma<<<2*DDIM*(HDIM/4), 256, smF>>>(out);
}

// round 17
// speedup vs baseline: 1.0628x; 1.0021x over previous
#include <cuda_runtime.h>
#include <cstdint>

#define CB 96
#define DDIM 8
#define HDIM 56
#define WDIM 56
#define SP   (DDIM*HDIM*WDIM)   // 25088
#define HWs  (HDIM*WDIM)        // 3136
#define NT   392                // tokens per window
#define NTP  400                // padded tokens
#define NWIN 128                // total windows (B=2, 64 per batch)
#define NTOK (NWIN*NT)          // 50176

__device__ __forceinline__ float to_tf32(float x) {
    unsigned u;
    asm("cvt.rna.tf32.f32 %0, %1;" : "=r"(u) : "f"(x));
    return __uint_as_float(u);
}

__device__ __forceinline__ void mma_tf32(float* c, const unsigned* a, unsigned b0, unsigned b1) {
    asm volatile(
        "mma.sync.aligned.m16n8k8.row.col.f32.tf32.tf32.f32 "
        "{%0,%1,%2,%3}, {%4,%5,%6,%7}, {%8,%9}, {%0,%1,%2,%3};\n"
        : "+f"(c[0]), "+f"(c[1]), "+f"(c[2]), "+f"(c[3])
        : "r"(a[0]), "r"(a[1]), "r"(a[2]), "r"(a[3]), "r"(b0), "r"(b1));
}

// token id -> spatial base offset (window reverse + un-roll), channel 0
__device__ __forceinline__ size_t tok_to_spatial(int t) {
    int win = t / NT, n = t % NT;
    int bb = win >> 6; int whi = (win & 63) >> 3, wwi = win & 7;
    int dz = n/49, r = n%49, hy = r/7, wl = r%7;
    int hs = whi*7 + hy, ws = wwi*7 + wl;
    int d0 = (dz + 4) & 7;
    int h0 = hs + 3; if (h0 >= HDIM) h0 -= HDIM;
    int w0 = ws + 3; if (w0 >= WDIM) w0 -= WDIM;
    return (size_t)bb*CB*SP + (size_t)d0*HWs + h0*WDIM + w0;
}

// ---------------- scratch (device globals; no allocation) ----------------
__device__ float g_xw  [NTOK*CB];
__device__ float g_qkv0[NTOK*288];
__device__ float g_qkv1[NTOK*288];
__device__ float g_o0  [NTOK*CB];
__device__ float g_o1  [NTOK*CB];
__device__ float g_x1  [2*CB*SP];
__device__ float g_x2  [2*CB*SP];     // LN2(x1), tf32-rounded
__device__ float g_weff[9*CB*3*CB];   // [k][co], tf32-rounded
__device__ float g_beff[CB];
__device__ float g_bias[4*9*NTP*NTP]; // [class][head9][i][j]

// ---------------- LN1 + shift-roll + window partition (v2) ----------------
__global__ void k_ln1(const float* __restrict__ x,
                      const float* __restrict__ lw, const float* __restrict__ lb) {
    __shared__ float row[WDIM*97];
    __shared__ float s_mu[WDIM], s_ri[WDIM];
    int bid = blockIdx.x;
    int h = bid % HDIM; int t = bid / HDIM; int d = t & 7; int bb = t >> 3;
    const float* base = x + (size_t)bb*CB*SP + d*HWs + h*WDIM;
    for (int i = threadIdx.x; i < CB*WDIM; i += 256) {
        int c = i / WDIM, w = i % WDIM;
        row[w*97 + c] = base[(size_t)c*SP + w];
    }
    __syncthreads();
    if (threadIdx.x < 4*WDIM) {
        int w = threadIdx.x >> 2, part = threadIdx.x & 3;
        float s = 0.f, s2 = 0.f;
        const float* rp = row + w*97 + part*24;
        #pragma unroll 6
        for (int k = 0; k < 24; k++) { float v = rp[k]; s += v; s2 += v*v; }
        s  += __shfl_xor_sync(0xffffffffu, s, 1);  s  += __shfl_xor_sync(0xffffffffu, s, 2);
        s2 += __shfl_xor_sync(0xffffffffu, s2, 1); s2 += __shfl_xor_sync(0xffffffffu, s2, 2);
        if (part == 0) {
            float mu = s * (1.0f/CB);
            s_mu[w] = mu;
            s_ri[w] = rsqrtf(s2 * (1.0f/CB) - mu*mu + 1e-5f);
        }
    }
    __syncthreads();
    int ds = (d + 4) & 7;
    for (int i = threadIdx.x; i < CB*WDIM; i += 256) {
        int w = i / CB, c = i % CB;
        int hs = h - 3; if (hs < 0) hs += HDIM;
        int ws = w - 3; if (ws < 0) ws += WDIM;
        int win = bb*64 + (hs/7)*8 + (ws/7);
        int n   = ds*49 + (hs%7)*7 + (ws%7);
        g_xw[((size_t)win*NT + n)*CB + c] =
            (row[w*97 + c] - s_mu[w]) * s_ri[w] * lw[c] + lb[c];
    }
}

// ---------------- GEMM via tf32 mma (A direct from global, prefetched) -------
#define WSTG 104   // Ws [k][n] stride
__global__ void __launch_bounds__(256) k_gemm_mma(const float* __restrict__ A,
                                                  const float* __restrict__ W,
                                                  const float* __restrict__ bias,
                                                  float* __restrict__ Out, int Ntot) {
    extern __shared__ float sm[];
    float* Ws = sm;                 // 96*WSTG
    int m0 = blockIdx.x * 128;
    int n0 = blockIdx.y * 96;
    int tid = threadIdx.x, warp = tid >> 5, lane = tid & 31;
    int lg = lane >> 2, lq = lane & 3;

    for (int i = tid; i < 96*24; i += 256) {
        int n = i / 24, c4 = i % 24;
        float4 v = *(const float4*)(W + (size_t)(n0 + n)*CB + c4*4);
        Ws[(c4*4+0)*WSTG + n] = to_tf32(v.x);
        Ws[(c4*4+1)*WSTG + n] = to_tf32(v.y);
        Ws[(c4*4+2)*WSTG + n] = to_tf32(v.z);
        Ws[(c4*4+3)*WSTG + n] = to_tf32(v.w);
    }
    __syncthreads();

    float c[12][4];
    #pragma unroll
    for (int nt = 0; nt < 12; nt++) { c[nt][0]=0.f; c[nt][1]=0.f; c[nt][2]=0.f; c[nt][3]=0.f; }

    int r0 = m0 + warp*16 + lg;
    const float* ap0 = A + (size_t)r0*CB + lq;
    const float* ap1 = ap0 + 8*CB;

    unsigned a[4];
    a[0] = __float_as_uint(to_tf32(ap0[0]));
    a[1] = __float_as_uint(to_tf32(ap1[0]));
    a[2] = __float_as_uint(to_tf32(ap0[4]));
    a[3] = __float_as_uint(to_tf32(ap1[4]));

    #pragma unroll
    for (int ks = 0; ks < 12; ks++) {
        unsigned an[4];
        if (ks < 11) {
            int kb = (ks + 1)*8;
            an[0] = __float_as_uint(to_tf32(ap0[kb]));
            an[1] = __float_as_uint(to_tf32(ap1[kb]));
            an[2] = __float_as_uint(to_tf32(ap0[kb + 4]));
            an[3] = __float_as_uint(to_tf32(ap1[kb + 4]));
        }
        int kb = ks*8;
        #pragma unroll
        for (int nt = 0; nt < 12; nt++) {
            const float* bp = Ws + (kb + lq)*WSTG + nt*8 + lg;
            unsigned b0 = __float_as_uint(bp[0]);
            unsigned b1 = __float_as_uint(bp[4*WSTG]);
            mma_tf32(c[nt], a, b0, b1);
        }
        if (ks < 11) { a[0] = an[0]; a[1] = an[1]; a[2] = an[2]; a[3] = an[3]; }
    }

    #pragma unroll
    for (int nt = 0; nt < 12; nt++) {
        int nc = n0 + nt*8 + lq*2;
        float2 bv = *(const float2*)(bias + nc);
        *(float2*)(Out + (size_t)r0*Ntot + nc)
            = make_float2(c[nt][0] + bv.x, c[nt][1] + bv.y);
        *(float2*)(Out + (size_t)(r0 + 8)*Ntot + nc)
            = make_float2(c[nt][2] + bv.x, c[nt][3] + bv.y);
    }
}

// ---------------- bias+mask table precompute ----------------
__global__ void k_bias(const float* __restrict__ rpb0, const float* __restrict__ rpb1) {
    int bid = blockIdx.x;
    int i = bid % NTP; int rest = bid / NTP;
    int head = rest % 9; int cls = rest / 9;
    int j = threadIdx.x;
    float v;
    if (i >= NT || j >= NT) {
        v = -1e9f;
    } else {
        int dzi = i/49, ri = i%49, hyi = ri/7, wli = ri%7;
        int dzj = j/49, rj = j%49, hyj = rj/7, wlj = rj%7;
        int idx = (dzi - dzj + 7)*169 + (hyi - hyj + 6)*13 + (wli - wlj + 6);
        float b = (head < 3) ? rpb0[idx*3 + head] : rpb1[idx*6 + head - 3];
        int ha = cls >> 1, wa = cls & 1;
        int hri = ha ? (hyi < 4 ? 1 : 2) : 0;
        int wri = wa ? (wli < 4 ? 1 : 2) : 0;
        int hrj = ha ? (hyj < 4 ? 1 : 2) : 0;
        int wrj = wa ? (wlj < 4 ? 1 : 2) : 0;
        int li = (dzi < 4 ? 0 : 1)*9 + hri*3 + wri;
        int lj = (dzj < 4 ? 0 : 1)*9 + hrj*3 + wrj;
        v = b + ((li != lj) ? -100.f : 0.f);
    }
    g_bias[((size_t)(cls*9 + head)*NTP + i)*NTP + j] = v;
}

// ---------------- windowed attention: tf32 mma + flash softmax ---------------
template<int DH, int NH, int HOFF, int MAXB, int NTHR>
__global__ void __launch_bounds__(NTHR, MAXB) k_attn_mma(const float* __restrict__ qkv,
                                                         float* __restrict__ outp) {
    constexpr int NW  = NTHR/32;
    constexpr int KST = 408;
    constexpr int VST = (DH == 32) ? 40 : 24;
    constexpr int PST = 84;
    constexpr int NKS = DH/8;
    constexpr int NVT = DH/8;
    extern __shared__ float sm[];
    float* Ksm = sm;
    float* Vsm = Ksm + DH*KST;
    float* Psm = Vsm + NTP*VST;

    int win = blockIdx.x / NH, hd = blockIdx.x % NH;
    const float* qb = qkv + (size_t)win*NT*288;
    int tid = threadIdx.x, warp = tid >> 5, lane = tid & 31;
    int lg = lane >> 2, lq = lane & 3;
    const float scale = rsqrtf((float)DH);

    for (int idx = tid; idx < NTP*(DH/4); idx += NTHR) {
        int n = idx / (DH/4), d4 = (idx % (DH/4))*4;
        if (n < NT) {
            float4 kv = *(const float4*)(qb + (size_t)n*288 + 96 + hd*DH + d4);
            Ksm[(d4+0)*KST + n] = to_tf32(kv.x);
            Ksm[(d4+1)*KST + n] = to_tf32(kv.y);
            Ksm[(d4+2)*KST + n] = to_tf32(kv.z);
            Ksm[(d4+3)*KST + n] = to_tf32(kv.w);
        } else {
            Ksm[(d4+0)*KST + n] = 0.f;
            Ksm[(d4+1)*KST + n] = 0.f;
            Ksm[(d4+2)*KST + n] = 0.f;
            Ksm[(d4+3)*KST + n] = 0.f;
        }
    }
    for (int idx = tid; idx < NTP*(DH/4); idx += NTHR) {
        int j = idx / (DH/4), d4 = (idx % (DH/4))*4;
        float4 vv = make_float4(0.f, 0.f, 0.f, 0.f);
        if (j < NT) {
            float4 t4 = *(const float4*)(qb + (size_t)j*288 + 192 + hd*DH + d4);
            vv = make_float4(to_tf32(t4.x), to_tf32(t4.y), to_tf32(t4.z), to_tf32(t4.w));
        }
        *(float4*)(Vsm + j*VST + d4) = vv;
    }
    __syncthreads();

    int cls = ((((win & 63) >> 3) == 7) ? 2 : 0) | (((win & 7) == 7) ? 1 : 0);
    const float* bias = g_bias + (size_t)(cls*9 + HOFF + hd)*(NTP*NTP);
    float* pwarp = Psm + warp*(16*PST);

    for (int tr = warp; tr < 25; tr += NW) {
        int i0 = tr*16;
        int r0 = i0 + lg;
        int r1 = min(i0 + lg + 8, NT - 1);
        unsigned qa[NKS][4];
        #pragma unroll
        for (int ks = 0; ks < NKS; ks++) {
            int d = ks*8 + lq;
            qa[ks][0] = __float_as_uint(to_tf32(qb[(size_t)r0*288 + hd*DH + d]     * scale));
            qa[ks][1] = __float_as_uint(to_tf32(qb[(size_t)r1*288 + hd*DH + d]     * scale));
            qa[ks][2] = __float_as_uint(to_tf32(qb[(size_t)r0*288 + hd*DH + d + 4] * scale));
            qa[ks][3] = __float_as_uint(to_tf32(qb[(size_t)r1*288 + hd*DH + d + 4] * scale));
        }
        float m0 = -1e30f, m1 = -1e30f, l0 = 0.f, l1 = 0.f;
        float O[NVT][4];
        #pragma unroll
        for (int nt = 0; nt < NVT; nt++) { O[nt][0]=0.f; O[nt][1]=0.f; O[nt][2]=0.f; O[nt][3]=0.f; }

        #pragma unroll
        for (int ch = 0; ch < 5; ch++) {
            int j0 = ch*80;
            float c[10][4];
            #pragma unroll
            for (int nt = 0; nt < 10; nt++) { c[nt][0]=0.f; c[nt][1]=0.f; c[nt][2]=0.f; c[nt][3]=0.f; }
            #pragma unroll
            for (int ks = 0; ks < NKS; ks++) {
                #pragma unroll
                for (int nt = 0; nt < 10; nt++) {
                    const float* bp = Ksm + (ks*8 + lq)*KST + j0 + nt*8 + lg;
                    unsigned b0 = __float_as_uint(bp[0]);
                    unsigned b1 = __float_as_uint(bp[4*KST]);
                    mma_tf32(c[nt], qa[ks], b0, b1);
                }
            }
            #pragma unroll
            for (int nt = 0; nt < 10; nt++) {
                const float* br0 = bias + (size_t)(i0 + lg)*NTP + j0 + nt*8 + lq*2;
                float2 b0v = *(const float2*)br0;
                float2 b1v = *(const float2*)(br0 + 8*NTP);
                c[nt][0] += b0v.x; c[nt][1] += b0v.y;
                c[nt][2] += b1v.x; c[nt][3] += b1v.y;
            }
            float cm0 = -1e30f, cm1 = -1e30f;
            #pragma unroll
            for (int nt = 0; nt < 10; nt++) {
                cm0 = fmaxf(cm0, fmaxf(c[nt][0], c[nt][1]));
                cm1 = fmaxf(cm1, fmaxf(c[nt][2], c[nt][3]));
            }
            cm0 = fmaxf(cm0, __shfl_xor_sync(0xffffffffu, cm0, 1));
            cm0 = fmaxf(cm0, __shfl_xor_sync(0xffffffffu, cm0, 2));
            cm1 = fmaxf(cm1, __shfl_xor_sync(0xffffffffu, cm1, 1));
            cm1 = fmaxf(cm1, __shfl_xor_sync(0xffffffffu, cm1, 2));
            float mn0 = fmaxf(m0, cm0), mn1 = fmaxf(m1, cm1);
            float s0 = __expf(m0 - mn0), s1 = __expf(m1 - mn1);
            m0 = mn0; m1 = mn1;
            l0 *= s0; l1 *= s1;
            #pragma unroll
            for (int nt = 0; nt < NVT; nt++) {
                O[nt][0] *= s0; O[nt][1] *= s0;
                O[nt][2] *= s1; O[nt][3] *= s1;
            }
            float sum0 = 0.f, sum1 = 0.f;
            #pragma unroll
            for (int nt = 0; nt < 10; nt++) {
                c[nt][0] = to_tf32(__expf(c[nt][0] - m0)); sum0 += c[nt][0];
                c[nt][1] = to_tf32(__expf(c[nt][1] - m0)); sum0 += c[nt][1];
                c[nt][2] = to_tf32(__expf(c[nt][2] - m1)); sum1 += c[nt][2];
                c[nt][3] = to_tf32(__expf(c[nt][3] - m1)); sum1 += c[nt][3];
            }
            sum0 += __shfl_xor_sync(0xffffffffu, sum0, 1);
            sum0 += __shfl_xor_sync(0xffffffffu, sum0, 2);
            sum1 += __shfl_xor_sync(0xffffffffu, sum1, 1);
            sum1 += __shfl_xor_sync(0xffffffffu, sum1, 2);
            l0 += sum0; l1 += sum1;
            #pragma unroll
            for (int nt = 0; nt < 10; nt++) {
                int jl = nt*8 + lq*2;
                *(float2*)(pwarp + lg*PST + jl)     = make_float2(c[nt][0], c[nt][1]);
                *(float2*)(pwarp + (lg+8)*PST + jl) = make_float2(c[nt][2], c[nt][3]);
            }
            __syncwarp();
            #pragma unroll
            for (int ks = 0; ks < 10; ks++) {
                unsigned pa[4];
                const float* pp = pwarp + lg*PST + ks*8 + lq;
                pa[0] = __float_as_uint(pp[0]);
                pa[1] = __float_as_uint(pp[8*PST]);
                pa[2] = __float_as_uint(pp[4]);
                pa[3] = __float_as_uint(pp[8*PST + 4]);
                #pragma unroll
                for (int nt = 0; nt < NVT; nt++) {
                    const float* vp = Vsm + (j0 + ks*8 + lq)*VST + nt*8 + lg;
                    unsigned b0 = __float_as_uint(vp[0]);
                    unsigned b1 = __float_as_uint(vp[4*VST]);
                    mma_tf32(O[nt], pa, b0, b1);
                }
            }
            __syncwarp();
        }
        float li0 = 1.f / l0, li1 = 1.f / l1;
        int ir0 = i0 + lg, ir1 = i0 + lg + 8;
        #pragma unroll
        for (int nt = 0; nt < NVT; nt++) {
            *(float2*)(outp + ((size_t)win*NT + ir0)*CB + hd*DH + nt*8 + lq*2)
                = make_float2(O[nt][0]*li0, O[nt][1]*li0);
            if (ir1 < NT)
                *(float2*)(outp + ((size_t)win*NT + ir1)*CB + hd*DH + nt*8 + lq*2)
                    = make_float2(O[nt][2]*li1, O[nt][3]*li1);
        }
    }
}

// ---------------- fused proj0+proj1 + NAS mix + reverse + residual + LN2 -----
__global__ void __launch_bounds__(256) k_projmix(
    const float* __restrict__ o0, const float* __restrict__ o1,
    const float* __restrict__ pw0, const float* __restrict__ pb0,
    const float* __restrict__ pw1, const float* __restrict__ pb1,
    const float* __restrict__ lnw, const float* __restrict__ lnb,
    const float* __restrict__ alpha, const float* __restrict__ x) {
    extern __shared__ float sm[];
    float* Ws0 = sm;                 // 96*WSTG
    float* Ws1 = sm + 96*WSTG;
    int m0 = blockIdx.x * 128;
    int tid = threadIdx.x, warp = tid >> 5, lane = tid & 31;
    int lg = lane >> 2, lq = lane & 3;

    for (int i = tid; i < 96*24; i += 256) {
        int n = i / 24, c4 = i % 24;
        float4 v0 = *(const float4*)(pw0 + (size_t)n*CB + c4*4);
        Ws0[(c4*4+0)*WSTG + n] = to_tf32(v0.x);
        Ws0[(c4*4+1)*WSTG + n] = to_tf32(v0.y);
        Ws0[(c4*4+2)*WSTG + n] = to_tf32(v0.z);
        Ws0[(c4*4+3)*WSTG + n] = to_tf32(v0.w);
        float4 v1 = *(const float4*)(pw1 + (size_t)n*CB + c4*4);
        Ws1[(c4*4+0)*WSTG + n] = to_tf32(v1.x);
        Ws1[(c4*4+1)*WSTG + n] = to_tf32(v1.y);
        Ws1[(c4*4+2)*WSTG + n] = to_tf32(v1.z);
        Ws1[(c4*4+3)*WSTG + n] = to_tf32(v1.w);
    }
    __syncthreads();

    float c0[12][4], c1[12][4];
    #pragma unroll
    for (int nt = 0; nt < 12; nt++) {
        c0[nt][0]=0.f; c0[nt][1]=0.f; c0[nt][2]=0.f; c0[nt][3]=0.f;
        c1[nt][0]=0.f; c1[nt][1]=0.f; c1[nt][2]=0.f; c1[nt][3]=0.f;
    }

    int t0 = m0 + warp*16 + lg, t1 = t0 + 8;
    const float* a00 = o0 + (size_t)t0*CB + lq;
    const float* a01 = o0 + (size_t)t1*CB + lq;
    const float* a10 = o1 + (size_t)t0*CB + lq;
    const float* a11 = o1 + (size_t)t1*CB + lq;
    #pragma unroll
    for (int ks = 0; ks < 12; ks++) {
        int kb = ks*8;
        unsigned aA[4], aB[4];
        aA[0] = __float_as_uint(to_tf32(a00[kb]));
        aA[1] = __float_as_uint(to_tf32(a01[kb]));
        aA[2] = __float_as_uint(to_tf32(a00[kb + 4]));
        aA[3] = __float_as_uint(to_tf32(a01[kb + 4]));
        aB[0] = __float_as_uint(to_tf32(a10[kb]));
        aB[1] = __float_as_uint(to_tf32(a11[kb]));
        aB[2] = __float_as_uint(to_tf32(a10[kb + 4]));
        aB[3] = __float_as_uint(to_tf32(a11[kb + 4]));
        #pragma unroll
        for (int nt = 0; nt < 12; nt++) {
            const float* bp0 = Ws0 + (kb + lq)*WSTG + nt*8 + lg;
            mma_tf32(c0[nt], aA, __float_as_uint(bp0[0]), __float_as_uint(bp0[4*WSTG]));
            const float* bp1 = Ws1 + (kb + lq)*WSTG + nt*8 + lg;
            mma_tf32(c1[nt], aB, __float_as_uint(bp1[0]), __float_as_uint(bp1[4*WSTG]));
        }
    }

    float al0 = alpha[0], al1 = alpha[1];
    float am = fmaxf(al0, al1);
    float e0 = __expf(al0 - am), e1 = __expf(al1 - am);
    float ai = 1.f / (e0 + e1);
    float aw0 = e0*ai, aw1 = e1*ai;

    #pragma unroll
    for (int nt = 0; nt < 12; nt++) {
        int cch = nt*8 + lq*2;
        float2 b0v = *(const float2*)(pb0 + cch);
        float2 b1v = *(const float2*)(pb1 + cch);
        c0[nt][0] = aw0*(c0[nt][0] + b0v.x) + aw1*(c1[nt][0] + b1v.x);
        c0[nt][1] = aw0*(c0[nt][1] + b0v.y) + aw1*(c1[nt][1] + b1v.y);
        c0[nt][2] = aw0*(c0[nt][2] + b0v.x) + aw1*(c1[nt][2] + b1v.x);
        c0[nt][3] = aw0*(c0[nt][3] + b0v.y) + aw1*(c1[nt][3] + b1v.y);
    }

    size_t sb0 = tok_to_spatial(t0);
    size_t sb1 = tok_to_spatial(t1);
    #pragma unroll
    for (int nt = 0; nt < 12; nt++) {
        int cch = nt*8 + lq*2;
        c0[nt][0] += x[sb0 + (size_t)cch*SP];
        c0[nt][1] += x[sb0 + (size_t)(cch+1)*SP];
        c0[nt][2] += x[sb1 + (size_t)cch*SP];
        c0[nt][3] += x[sb1 + (size_t)(cch+1)*SP];
    }

    float s0 = 0.f, q0 = 0.f, s1 = 0.f, q1 = 0.f;
    #pragma unroll
    for (int nt = 0; nt < 12; nt++) {
        s0 += c0[nt][0] + c0[nt][1];
        q0 += c0[nt][0]*c0[nt][0] + c0[nt][1]*c0[nt][1];
        s1 += c0[nt][2] + c0[nt][3];
        q1 += c0[nt][2]*c0[nt][2] + c0[nt][3]*c0[nt][3];
    }
    s0 += __shfl_xor_sync(0xffffffffu, s0, 1); s0 += __shfl_xor_sync(0xffffffffu, s0, 2);
    q0 += __shfl_xor_sync(0xffffffffu, q0, 1); q0 += __shfl_xor_sync(0xffffffffu, q0, 2);
    s1 += __shfl_xor_sync(0xffffffffu, s1, 1); s1 += __shfl_xor_sync(0xffffffffu, s1, 2);
    q1 += __shfl_xor_sync(0xffffffffu, q1, 1); q1 += __shfl_xor_sync(0xffffffffu, q1, 2);
    float mu0 = s0 * (1.0f/CB), mu1 = s1 * (1.0f/CB);
    float ri0 = rsqrtf(q0 * (1.0f/CB) - mu0*mu0 + 1e-5f);
    float ri1 = rsqrtf(q1 * (1.0f/CB) - mu1*mu1 + 1e-5f);

    #pragma unroll
    for (int nt = 0; nt < 12; nt++) {
        int cch = nt*8 + lq*2;
        float w0 = lnw[cch], w1 = lnw[cch+1];
        float b0 = lnb[cch], b1 = lnb[cch+1];
        g_x1[sb0 + (size_t)cch*SP]     = c0[nt][0];
        g_x1[sb0 + (size_t)(cch+1)*SP] = c0[nt][1];
        g_x1[sb1 + (size_t)cch*SP]     = c0[nt][2];
        g_x1[sb1 + (size_t)(cch+1)*SP] = c0[nt][3];
        g_x2[sb0 + (size_t)cch*SP]     = to_tf32((c0[nt][0] - mu0)*ri0*w0 + b0);
        g_x2[sb0 + (size_t)(cch+1)*SP] = to_tf32((c0[nt][1] - mu0)*ri0*w1 + b1);
        g_x2[sb1 + (size_t)cch*SP]     = to_tf32((c0[nt][2] - mu1)*ri1*w0 + b0);
        g_x2[sb1 + (size_t)(cch+1)*SP] = to_tf32((c0[nt][3] - mu1)*ri1*w1 + b1);
    }
}

// ---------------- build effective conv weights (NAS fold, tf32-rounded) ------
__global__ void k_weff(const float* __restrict__ c3w, const float* __restrict__ c3b,
                       const float* __restrict__ c1w, const float* __restrict__ c1b,
                       const float* __restrict__ dww, const float* __restrict__ dwb,
                       const float* __restrict__ alpha) {
    float a[4]; float m = -1e30f;
    #pragma unroll
    for (int i = 0; i < 4; i++) { a[i] = alpha[i]; m = fmaxf(m, a[i]); }
    float s = 0.f;
    #pragma unroll
    for (int i = 0; i < 4; i++) { a[i] = __expf(a[i] - m); s += a[i]; }
    float inv = 1.f / s;
    #pragma unroll
    for (int i = 0; i < 4; i++) a[i] *= inv;
    int total = CB*CB*27;
    for (int idx = blockIdx.x*blockDim.x + threadIdx.x; idx < total; idx += gridDim.x*blockDim.x) {
        int t = idx % 27; int rest = idx / 27; int ci = rest % CB; int co = rest / CB;
        float val = a[0] * c3w[idx];
        if (t == 13)            val += a[1] * c1w[co*CB + ci];
        if (ci == co)           val += a[2] * dww[co*27 + t];
        if (t == 13 && ci == co) val += a[3];
        int tt = t / 3, tw = t % 3;
        g_weff[(((size_t)tt*CB + ci)*3 + tw)*CB + co] = to_tf32(val);
    }
    int gid = blockIdx.x*blockDim.x + threadIdx.x;
    if (gid < CB) g_beff[gid] = a[0]*c3b[gid] + a[1]*c1b[gid] + a[2]*dwb[gid];
}

// ---------------- FFN as tf32 implicit-GEMM mma + residual (double-buffered) -
#define KCH 32
#define AST 104
#define BST 232
#define FBUF (KCH*AST + KCH*BST)   // 10752 floats per buffer

__global__ void __launch_bounds__(256) k_ffn_mma(float* __restrict__ out) {
    extern __shared__ float sm[];
    int bid = blockIdx.x;
    int h4 = bid % 14; int t = bid / 14; int d = t & 7; int bb = t >> 3;
    int h0 = h4*4;
    int tid = threadIdx.x;
    int warp = tid >> 5, lane = tid & 31;
    int wm = warp >> 2, wn = warp & 3;
    int lg = lane >> 2, lq = lane & 3;
    int kk = tid >> 3, nlane = tid & 7;

    float acc[3][7][4];
    #pragma unroll
    for (int mt = 0; mt < 3; mt++) {
        int m = wm*48 + mt*16 + lg;
        float b0 = g_beff[m], b8 = g_beff[m + 8];
        #pragma unroll
        for (int nt = 0; nt < 7; nt++) {
            acc[mt][nt][0] = b0; acc[mt][nt][1] = b0;
            acc[mt][nt][2] = b8; acc[mt][nt][3] = b8;
        }
    }

    auto stage = [&](int buf, int kc) {
        float* As = sm + buf*FBUF;
        float* Bs = As + KCH*AST;
        #pragma unroll
        for (int s = 0; s < 12; s++) {
            int i = tid + s*256;
            int k = i / 96, co = i % 96;
            As[k*AST + co] = g_weff[(size_t)(kc*KCH + k)*CB + co];
        }
        int kg = kc*KCH + kk;
        int tt = kg / 288; int r = kg % 288; int ci = r / 3; int tw = r % 3;
        int td = tt / 3, th = tt % 3;
        int sd = d + td - 1;
        bool dok = (unsigned)sd < 8u;
        const float* rowp[4]; bool rok[4];
        #pragma unroll
        for (int hr = 0; hr < 4; hr++) {
            int sh = h0 + hr + th - 1;
            rok[hr] = dok && (unsigned)sh < 56u;
            rowp[hr] = g_x2 + ((size_t)(bb*CB + ci)*DDIM + sd)*HWs + sh*WDIM + (tw - 1);
        }
        float* bdst = Bs + kk*BST;
        #pragma unroll
        for (int j = 0; j < 28; j++) {
            const int hr = (j*8) / 56;
            const int wb = (j*8) % 56;
            int w = wb + nlane;
            bool ok = rok[hr] && ((unsigned)(w + tw - 1) < 56u);
            bdst[j*8 + nlane] = ok ? rowp[hr][w] : 0.f;
        }
    };

    stage(0, 0);
    for (int kc = 0; kc < 81; kc++) {
        __syncthreads();
        if (kc < 80) stage((kc + 1) & 1, kc + 1);
        const float* As = sm + (kc & 1)*FBUF;
        const float* Bs = As + KCH*AST;
        #pragma unroll
        for (int k8 = 0; k8 < 4; k8++) {
            int kb = k8*8;
            unsigned a[3][4];
            #pragma unroll
            for (int mt = 0; mt < 3; mt++) {
                const float* ap = As + (kb + lq)*AST + wm*48 + mt*16 + lg;
                a[mt][0] = __float_as_uint(ap[0]);
                a[mt][1] = __float_as_uint(ap[8]);
                a[mt][2] = __float_as_uint(ap[4*AST]);
                a[mt][3] = __float_as_uint(ap[4*AST + 8]);
            }
            #pragma unroll
            for (int nt = 0; nt < 7; nt++) {
                const float* bp = Bs + (kb + lq)*BST + wn*56 + nt*8 + lg;
                unsigned b0 = __float_as_uint(bp[0]);
                unsigned b1 = __float_as_uint(bp[4*BST]);
                mma_tf32(acc[0][nt], a[0], b0, b1);
                mma_tf32(acc[1][nt], a[1], b0, b1);
                mma_tf32(acc[2][nt], a[2], b0, b1);
            }
        }
    }

    int hrow = h0 + wn;
    #pragma unroll
    for (int mt = 0; mt < 3; mt++) {
        int m = wm*48 + mt*16 + lg;
        size_t base = ((size_t)(bb*CB + m)*DDIM + d)*HWs + hrow*WDIM;
        #pragma unroll
        for (int nt = 0; nt < 7; nt++) {
            int w0 = nt*8 + lq*2;
            size_t i0 = base + w0;
            size_t i1 = i0 + (size_t)8*SP;
            float2 r0 = *(const float2*)(g_x1 + i0);
            float2 r1 = *(const float2*)(g_x1 + i1);
            float2 o0 = make_float2(r0.x + acc[mt][nt][0], r0.y + acc[mt][nt][1]);
            float2 o1 = make_float2(r1.x + acc[mt][nt][2], r1.y + acc[mt][nt][3]);
            *(float2*)(out + i0) = o0;
            *(float2*)(out + i1) = o1;
        }
    }
}

// ---------------- host launch (capture-legal two-stream fork/join) -----------
extern "C" void kernel_launch(void* const* d_in, const int* in_sizes, int n_in,
                              void* d_out, int out_size) {
    (void)in_sizes; (void)n_in; (void)out_size;
    const float* x      = (const float*)d_in[0];
    const float* ln1w   = (const float*)d_in[1];
    const float* ln1b   = (const float*)d_in[2];
    const float* ln2w   = (const float*)d_in[3];
    const float* ln2b   = (const float*)d_in[4];
    const float* qkvw0  = (const float*)d_in[5];
    const float* qkvb0  = (const float*)d_in[6];
    const float* projw0 = (const float*)d_in[7];
    const float* projb0 = (const float*)d_in[8];
    const float* rpb0   = (const float*)d_in[9];
    const float* qkvw1  = (const float*)d_in[10];
    const float* qkvb1  = (const float*)d_in[11];
    const float* projw1 = (const float*)d_in[12];
    const float* projb1 = (const float*)d_in[13];
    const float* rpb1   = (const float*)d_in[14];
    const float* alphaA = (const float*)d_in[15];
    const float* c3w    = (const float*)d_in[16];
    const float* c3b    = (const float*)d_in[17];
    const float* c1w    = (const float*)d_in[18];
    const float* c1b    = (const float*)d_in[19];
    const float* dww    = (const float*)d_in[20];
    const float* dwb    = (const float*)d_in[21];
    const float* alphaF = (const float*)d_in[22];
    float* out = (float*)d_out;

    float *p_xw, *p_q0, *p_q1, *p_o0, *p_o1;
    cudaGetSymbolAddress((void**)&p_xw, g_xw);
    cudaGetSymbolAddress((void**)&p_q0, g_qkv0);
    cudaGetSymbolAddress((void**)&p_q1, g_qkv1);
    cudaGetSymbolAddress((void**)&p_o0, g_o0);
    cudaGetSymbolAddress((void**)&p_o1, g_o1);

    int smG  = (96*WSTG) * 4;                       // 39936 B
    int smP  = (2*96*WSTG) * 4;                     // 79872 B
    int smA0 = (32*408 + NTP*40 + 12*16*84) * 4;    // 180736 B (12 warps)
    int smA1 = (16*408 + NTP*24 + 8*16*84) * 4;     // 107520 B
    int smF  = 2*FBUF*4;                            // 86016 B
    cudaFuncSetAttribute((const void*)k_gemm_mma,
                         cudaFuncAttributeMaxDynamicSharedMemorySize, smG);
    cudaFuncSetAttribute((const void*)k_projmix,
                         cudaFuncAttributeMaxDynamicSharedMemorySize, smP);
    cudaFuncSetAttribute((const void*)k_attn_mma<32,3,0,1,384>,
                         cudaFuncAttributeMaxDynamicSharedMemorySize, smA0);
    cudaFuncSetAttribute((const void*)k_attn_mma<16,6,3,2,256>,
                         cudaFuncAttributeMaxDynamicSharedMemorySize, smA1);
    cudaFuncSetAttribute((const void*)k_ffn_mma,
                         cudaFuncAttributeMaxDynamicSharedMemorySize, smF);

    // side stream + events: created once, outside capture.
    static cudaStream_t s2 = nullptr;
    static cudaEvent_t  eFork = nullptr, eLn1 = nullptr, eBias = nullptr, eJoin = nullptr;
    if (s2 == nullptr) {
        cudaStreamCreateWithFlags(&s2, cudaStreamNonBlocking);
        cudaEventCreateWithFlags(&eFork, cudaEventDisableTiming);
        cudaEventCreateWithFlags(&eLn1,  cudaEventDisableTiming);
        cudaEventCreateWithFlags(&eBias, cudaEventDisableTiming);
        cudaEventCreateWithFlags(&eJoin, cudaEventDisableTiming);
    }

    dim3 gq(NTOK/128, 3);

    // ---- fork: s2 joins the capture via eFork recorded on origin stream ----
    cudaEventRecord(eFork, 0);
    cudaStreamWaitEvent(s2, eFork, 0);

    // ---- s2: independent prework (bias table, weff) ----
    k_bias<<<4*9*NTP, NTP, 0, s2>>>(rpb0, rpb1);
    cudaEventRecord(eBias, s2);
    k_weff<<<128, 256, 0, s2>>>(c3w, c3b, c1w, c1b, dww, dwb, alphaF);

    // ---- default: ln1 -> qkv0 ----
    k_ln1<<<2*DDIM*HDIM, 256>>>(x, ln1w, ln1b);
    cudaEventRecord(eLn1, 0);
    k_gemm_mma<<<gq, 256, smG>>>(p_xw, qkvw0, qkvb0, p_q0, 288);

    // ---- s2: qkv1 -> attn1 (after ln1; bias already done on s2) ----
    cudaStreamWaitEvent(s2, eLn1, 0);
    k_gemm_mma<<<gq, 256, smG, s2>>>(p_xw, qkvw1, qkvb1, p_q1, 288);
    k_attn_mma<16,6,3,2,256><<<NWIN*6, 256, smA1, s2>>>(p_q1, p_o1);
    cudaEventRecord(eJoin, s2);

    // ---- default: attn0 (needs bias table) ----
    cudaStreamWaitEvent(0, eBias, 0);
    k_attn_mma<32,3,0,1,384><<<NWIN*3, 384, smA0>>>(p_q0, p_o0);

    // ---- join, then tail ----
    cudaStreamWaitEvent(0, eJoin, 0);
    k_projmix<<<NTOK/128, 256, smP>>>(p_o0, p_o1, projw0, projb0, projw1, projb1,
                                      ln2w, ln2b, alphaA, x);
    k_ffn_mma<<<2*DDIM*(HDIM/4), 256, smF>>>(out);
}